// round 12
// baseline (speedup 1.0000x reference)
#include <cuda_runtime.h>
#include <cuda_bf16.h>
#include <math.h>
#include <stdint.h>

// ---------------------------------------------------------------------------
// MoE + LoRA forward, routed top-2/8. Legacy mma.sync bf16 tensor path.
// Round 12: round-11 plan with the cvt fix (unpack f32x2 then bf16x2 pack).
// fold(+init) w/ packed f32x2 FMA; gather(+offsets); combine(+loss).
// gu_gemm is our launch index 3 => ncu-captured slot.
// ---------------------------------------------------------------------------

#define DIM    2048
#define T_TOK  8192
#define NE     8
#define NR     16
#define NROWS  (T_TOK*2)
#define PADROWS (NROWS + NE*128)      // per-expert counts padded to 128
#define MAXTILES (PADROWS/128)        // 136
#define SCALING 2.0f
#define AUXC   0.01f
#define ZC     0.001f

#define BK 64
#define NS 32                              // 2048 / 64 K-stages
#define GU_STG (128*64 + 64*64 + 64*64)    // halves/stage: A + Bg + Bu
#define D_STG  (128*64 + 128*64)           // halves/stage: A + B
#define GU_SMEM (3*GU_STG*2)               // 98304 B
#define D_SMEM  (3*D_STG*2)                // 98304 B

// ------------------------- scratch (device globals) ------------------------
__device__ int   g_counts[NE];
__device__ int   g_offsets[NE+1];     // padded cumulative offsets
__device__ int   g_tile_e[MAXTILES];
__device__ int   g_ntiles;
__device__ float g_importance[NE];
__device__ float g_zsum;
__device__ int   g_tok[NE*T_TOK];
__device__ int   g_re[NROWS];
__device__ int   g_rs[NROWS];
__device__ float g_rg[NROWS];

__device__ __nv_bfloat16 g_Xg[(size_t)PADROWS*DIM];    // gathered bf16 X rows
__device__ __nv_bfloat16 g_Wgb[(size_t)NE*DIM*DIM];    // folded bf16 weights
__device__ __nv_bfloat16 g_Wub[(size_t)NE*DIM*DIM];
__device__ __nv_bfloat16 g_Wdb[(size_t)NE*DIM*DIM];

__device__ __nv_bfloat16 g_A2[(size_t)PADROWS*DIM];    // silu(g)*u
__device__ __nv_bfloat16 g_D[(size_t)PADROWS*DIM];     // down output (bf16)

// ------------------------------- helpers -----------------------------------
__device__ __forceinline__ uint2 cvt4(float4 v) {
    __nv_bfloat162 lo = __floats2bfloat162_rn(v.x, v.y);
    __nv_bfloat162 hi = __floats2bfloat162_rn(v.z, v.w);
    uint2 r;
    r.x = *reinterpret_cast<unsigned*>(&lo);
    r.y = *reinterpret_cast<unsigned*>(&hi);
    return r;
}

__device__ __forceinline__ void mma16816(float* d, const unsigned* a, const unsigned* b) {
    asm volatile(
        "mma.sync.aligned.m16n8k16.row.col.f32.bf16.bf16.f32 "
        "{%0,%1,%2,%3}, {%4,%5,%6,%7}, {%8,%9}, {%0,%1,%2,%3};\n"
        : "+f"(d[0]), "+f"(d[1]), "+f"(d[2]), "+f"(d[3])
        : "r"(a[0]), "r"(a[1]), "r"(a[2]), "r"(a[3]), "r"(b[0]), "r"(b[1]));
}

__device__ __forceinline__ void ldsm4(unsigned &r0, unsigned &r1, unsigned &r2,
                                      unsigned &r3, uint32_t addr) {
    asm volatile("ldmatrix.sync.aligned.m8n8.x4.shared.b16 {%0,%1,%2,%3}, [%4];\n"
                 : "=r"(r0), "=r"(r1), "=r"(r2), "=r"(r3) : "r"(addr));
}

__device__ __forceinline__ void cpa16(uint32_t dst, const void* src) {
    asm volatile("cp.async.cg.shared.global [%0], [%1], 16;\n" :: "r"(dst), "l"(src));
}
#define CP_COMMIT asm volatile("cp.async.commit_group;\n")
template<int N> __device__ __forceinline__ void cp_wait() {
    asm volatile("cp.async.wait_group %0;\n" :: "n"(N));
}

// packed fp32x2 helpers (fma.rn.f32x2 verified to assemble on this toolchain)
__device__ __forceinline__ void fma2(uint64_t& d, uint64_t a, uint64_t b) {
    asm("fma.rn.f32x2 %0, %1, %2, %3;" : "=l"(d) : "l"(a), "l"(b), "l"(d));
}
__device__ __forceinline__ uint64_t packf2(float lo, float hi) {
    uint64_t r;
    asm("mov.b64 %0, {%1, %2};" : "=l"(r) : "f"(lo), "f"(hi));
    return r;
}
__device__ __forceinline__ void unpackf2(uint64_t p, float& lo, float& hi) {
    asm("mov.b64 {%0, %1}, %2;" : "=f"(lo), "=f"(hi) : "l"(p));
}

// ---------------- fold(+init): W' = bf16(W + SCALING * B @ A) ---------------
// One launch covers all three weight sets: blockIdx.z = wsel*NE + e.
// Designated block also zeroes the routing state (stream-ordered before router).
__global__ __launch_bounds__(256) void fold_kernel(
        const float* __restrict__ Wg_, const float* __restrict__ Ag_,
        const float* __restrict__ Bg_,
        const float* __restrict__ Wu_, const float* __restrict__ Au_,
        const float* __restrict__ Bu_,
        const float* __restrict__ Wd_, const float* __restrict__ Ad_,
        const float* __restrict__ Bd_,
        __nv_bfloat16* __restrict__ Og_, __nv_bfloat16* __restrict__ Ou_,
        __nv_bfloat16* __restrict__ Od_) {
    int z = blockIdx.z;
    if (z == 0 && blockIdx.x == 0 && blockIdx.y == 0) {
        int t = threadIdx.x;
        if (t < NE) { g_counts[t] = 0; g_importance[t] = 0.f; }
        if (t == 0) g_zsum = 0.f;
    }
    int wsel = z >> 3;          // 0=gate, 1=up, 2=down
    int e = z & 7;
    const float* W = (wsel == 0) ? Wg_ : (wsel == 1) ? Wu_ : Wd_;
    const float* A = (wsel == 0) ? Ag_ : (wsel == 1) ? Au_ : Ad_;
    const float* B = (wsel == 0) ? Bg_ : (wsel == 1) ? Bu_ : Bd_;
    __nv_bfloat16* out = (wsel == 0) ? Og_ : (wsel == 1) ? Ou_ : Od_;

    int tid = threadIdx.x;
    int n  = blockIdx.y * 64 + (tid >> 2);
    int k0 = blockIdx.x * 128;

    __shared__ float As[NR][128];
#pragma unroll
    for (int i = 0; i < 8; i++) {
        int idx = tid + i * 256;
        As[idx >> 7][idx & 127] = A[((size_t)e*NR + (idx >> 7))*DIM + k0 + (idx & 127)];
    }
    __syncthreads();

    uint64_t Brp[NR];
    {
        const float4* b4 = (const float4*)(B + ((size_t)e*DIM + n)*NR);
#pragma unroll
        for (int q = 0; q < 4; q++) {
            float4 v = b4[q];
            Brp[q*4+0] = packf2(SCALING * v.x, SCALING * v.x);
            Brp[q*4+1] = packf2(SCALING * v.y, SCALING * v.y);
            Brp[q*4+2] = packf2(SCALING * v.z, SCALING * v.z);
            Brp[q*4+3] = packf2(SCALING * v.w, SCALING * v.w);
        }
    }

    const float* Wrow = W + ((size_t)e*DIM + n)*DIM + k0;
    __nv_bfloat16* Orow = out + ((size_t)e*DIM + n)*DIM + k0;
#pragma unroll
    for (int q = 0; q < 8; q++) {
        int k = q*16 + (tid & 3)*4;    // interleaved: conflict-free smem banks
        float4 w = *(const float4*)(Wrow + k);
        uint64_t p01 = packf2(w.x, w.y);
        uint64_t p23 = packf2(w.z, w.w);
#pragma unroll
        for (int r = 0; r < NR; r++) {
            uint64_t a01 = *(const uint64_t*)&As[r][k];
            uint64_t a23 = *(const uint64_t*)&As[r][k+2];
            fma2(p01, Brp[r], a01);
            fma2(p23, Brp[r], a23);
        }
        float f0, f1, f2, f3;
        unpackf2(p01, f0, f1);
        unpackf2(p23, f2, f3);
        __nv_bfloat162 lo = __floats2bfloat162_rn(f0, f1);
        __nv_bfloat162 hi = __floats2bfloat162_rn(f2, f3);
        uint2 o;
        o.x = *reinterpret_cast<unsigned*>(&lo);
        o.y = *reinterpret_cast<unsigned*>(&hi);
        *(uint2*)(Orow + k) = o;
    }
}

// ------------------------------- routing ------------------------------------
__global__ void router_kernel(const float* __restrict__ X,
                              const float* __restrict__ Wg) {
    int warp = threadIdx.x >> 5, lane = threadIdx.x & 31;
    int t = blockIdx.x * 8 + warp;
    if (t >= T_TOK) return;
    const float4* xr = (const float4*)(X + (size_t)t * DIM);
    float acc[NE];
#pragma unroll
    for (int e = 0; e < NE; e++) acc[e] = 0.f;
    for (int i = lane; i < DIM/4; i += 32) {
        float4 xv = xr[i];
#pragma unroll
        for (int e = 0; e < NE; e++) {
            float4 w = ((const float4*)(Wg + (size_t)e * DIM))[i];
            acc[e] += xv.x*w.x + xv.y*w.y + xv.z*w.z + xv.w*w.w;
        }
    }
#pragma unroll
    for (int e = 0; e < NE; e++)
#pragma unroll
        for (int o = 16; o > 0; o >>= 1)
            acc[e] += __shfl_xor_sync(0xffffffffu, acc[e], o);

    if (lane == 0) {
        int e0 = 0;
#pragma unroll
        for (int e = 1; e < NE; e++) if (acc[e] > acc[e0]) e0 = e;
        int e1 = (e0 == 0) ? 1 : 0;
#pragma unroll
        for (int e = 0; e < NE; e++)
            if (e != e0 && acc[e] > acc[e1]) e1 = e;

        float m = acc[e0];
        float s = 0.f;
#pragma unroll
        for (int e = 0; e < NE; e++) s += expf(acc[e] - m);
        float lse = logf(s) + m;
        atomicAdd(&g_zsum, lse * lse);

        float d = expf(acc[e1] - acc[e0]);
        float p0 = 1.f / (1.f + d);
        float p1 = d / (1.f + d);

        int s0 = atomicAdd(&g_counts[e0], 1);
        int s1 = atomicAdd(&g_counts[e1], 1);
        g_tok[e0*T_TOK + s0] = t;
        g_tok[e1*T_TOK + s1] = t;
        atomicAdd(&g_importance[e0], p0);
        atomicAdd(&g_importance[e1], p1);
        g_re[2*t] = e0;  g_rs[2*t] = s0;  g_rg[2*t] = p0;
        g_re[2*t+1] = e1; g_rs[2*t+1] = s1; g_rg[2*t+1] = p1;
    }
}

// gather(+offsets): derive padded offsets from g_counts per block; block 0
// publishes g_offsets / g_tile_e / g_ntiles for downstream kernels.
__global__ void gather_kernel(const float* __restrict__ X) {
    int offs[NE+1];
    int o = 0;
#pragma unroll
    for (int e = 0; e < NE; e++) {
        offs[e] = o;
        o += ((g_counts[e] + 127) >> 7) << 7;
    }
    offs[NE] = o;

    if (blockIdx.x == 0) {
        int t = threadIdx.x;
        if (t <= NE) g_offsets[t] = offs[t];
        if (t == 0) g_ntiles = o >> 7;
        if (t < MAXTILES && t < (o >> 7)) {
            int te = 0;
#pragma unroll
            for (int e = 0; e < NE; e++)
                if (t*128 >= offs[e]) te = e;
            g_tile_e[t] = te;
        }
    }

    int row = blockIdx.x;
    if (row >= o) return;
    int e = 0;
#pragma unroll
    for (int q = 0; q < NE; q++)
        if (row >= offs[q]) e = q;
    int slot = row - offs[e];
    __nv_bfloat16* dst = g_Xg + (size_t)row * DIM;
    if (slot < g_counts[e]) {
        const float4* src = (const float4*)(X + (size_t)g_tok[e*T_TOK + slot] * DIM);
        for (int i = threadIdx.x; i < DIM/4; i += blockDim.x)
            *(uint2*)(dst + i*4) = cvt4(src[i]);
    } else {
        for (int i = threadIdx.x; i < DIM/4; i += blockDim.x)
            *(uint2*)(dst + i*4) = make_uint2(0u, 0u);
    }
}

// ----------------------- fused gate+up GEMM (mma.sync) ----------------------
// C_gate[128x64] and C_up[128x64] for the same (tile, n0); A tile shared.
__global__ __launch_bounds__(256, 2) void gu_gemm_kernel() {
    int tile = blockIdx.y;
    if (tile >= g_ntiles) return;
    int e = g_tile_e[tile];
    int rowbase = tile * 128;
    int n0 = blockIdx.x * 64;
    int tid = threadIdx.x;

    extern __shared__ __nv_bfloat16 smem[];
    uint32_t smBase = (uint32_t)__cvta_generic_to_shared(smem);

    auto loadStage = [&](int s) {
        uint32_t buf = smBase + (uint32_t)(s % 3) * (GU_STG * 2);
        int k0 = s * BK;
#pragma unroll
        for (int it = 0; it < 4; it++) {           // A: 1024 x 16B
            int c = tid + it * 256;
            int row = c >> 3, ch = c & 7;
            uint32_t d = buf + (uint32_t)(row*64 + ((ch ^ (row & 7)) * 8)) * 2;
            cpa16(d, g_Xg + (size_t)(rowbase + row)*DIM + k0 + ch*8);
        }
#pragma unroll
        for (int it = 0; it < 2; it++) {           // Bg: 512 x 16B
            int c = tid + it * 256;
            int row = c >> 3, ch = c & 7;
            uint32_t d = buf + (uint32_t)(8192 + row*64 + ((ch ^ (row & 7)) * 8)) * 2;
            cpa16(d, g_Wgb + ((size_t)e*DIM + n0 + row)*DIM + k0 + ch*8);
        }
#pragma unroll
        for (int it = 0; it < 2; it++) {           // Bu
            int c = tid + it * 256;
            int row = c >> 3, ch = c & 7;
            uint32_t d = buf + (uint32_t)(12288 + row*64 + ((ch ^ (row & 7)) * 8)) * 2;
            cpa16(d, g_Wub + ((size_t)e*DIM + n0 + row)*DIM + k0 + ch*8);
        }
    };

    float ag[2][4][4], au[2][4][4];
#pragma unroll
    for (int mt = 0; mt < 2; mt++)
#pragma unroll
        for (int nt = 0; nt < 4; nt++)
#pragma unroll
            for (int i = 0; i < 4; i++) { ag[mt][nt][i] = 0.f; au[mt][nt][i] = 0.f; }

    int lane = tid & 31, warp = tid >> 5;
    int wm = warp & 3, wn = warp >> 2;    // 4x2 warps; 32 rows x 32 cols each

    loadStage(0); CP_COMMIT;
    loadStage(1); CP_COMMIT;

    for (int s = 0; s < NS; s++) {
        cp_wait<1>();
        __syncthreads();
        if (s + 2 < NS) loadStage(s + 2);
        CP_COMMIT;

        uint32_t buf = smBase + (uint32_t)(s % 3) * (GU_STG * 2);
#pragma unroll
        for (int kk = 0; kk < BK; kk += 16) {
            int kh = kk + ((lane >> 4) << 3);
            unsigned af[2][4];
#pragma unroll
            for (int mt = 0; mt < 2; mt++) {
                int arow = wm*32 + mt*16 + (lane & 15);
                uint32_t a = buf + (uint32_t)(arow*64 +
                              (((kh >> 3) ^ (arow & 7)) << 3)) * 2;
                ldsm4(af[mt][0], af[mt][1], af[mt][2], af[mt][3], a);
            }
            unsigned bg[4][2];
#pragma unroll
            for (int p = 0; p < 2; p++) {
                int brow = wn*32 + p*16 + (lane & 15);
                uint32_t b = buf + (uint32_t)(8192 + brow*64 +
                              (((kh >> 3) ^ (brow & 7)) << 3)) * 2;
                unsigned q0, q1, q2, q3;
                ldsm4(q0, q1, q2, q3, b);
                bg[2*p][0] = q0; bg[2*p][1] = q2;
                bg[2*p+1][0] = q1; bg[2*p+1][1] = q3;
            }
#pragma unroll
            for (int mt = 0; mt < 2; mt++)
#pragma unroll
                for (int nt = 0; nt < 4; nt++)
                    mma16816(ag[mt][nt], af[mt], bg[nt]);
            unsigned bu[4][2];
#pragma unroll
            for (int p = 0; p < 2; p++) {
                int brow = wn*32 + p*16 + (lane & 15);
                uint32_t b = buf + (uint32_t)(12288 + brow*64 +
                              (((kh >> 3) ^ (brow & 7)) << 3)) * 2;
                unsigned q0, q1, q2, q3;
                ldsm4(q0, q1, q2, q3, b);
                bu[2*p][0] = q0; bu[2*p][1] = q2;
                bu[2*p+1][0] = q1; bu[2*p+1][1] = q3;
            }
#pragma unroll
            for (int mt = 0; mt < 2; mt++)
#pragma unroll
                for (int nt = 0; nt < 4; nt++)
                    mma16816(au[mt][nt], af[mt], bu[nt]);
        }
    }

    // epilogue: a = silu(g) * u -> g_A2 bf16
    int g = lane >> 2, t4 = lane & 3;
#pragma unroll
    for (int mt = 0; mt < 2; mt++) {
#pragma unroll
        for (int hrow = 0; hrow < 2; hrow++) {
            int r = wm*32 + mt*16 + g + hrow*8;
            __nv_bfloat16* dst = g_A2 + (size_t)(rowbase + r)*DIM + n0;
#pragma unroll
            for (int nt = 0; nt < 4; nt++) {
                int c = wn*32 + nt*8 + 2*t4;
                float g0 = ag[mt][nt][hrow*2 + 0];
                float g1 = ag[mt][nt][hrow*2 + 1];
                float u0 = au[mt][nt][hrow*2 + 0];
                float u1 = au[mt][nt][hrow*2 + 1];
                float a0 = g0 / (1.f + expf(-g0)) * u0;
                float a1 = g1 / (1.f + expf(-g1)) * u1;
                __nv_bfloat162 p = __floats2bfloat162_rn(a0, a1);
                *(unsigned*)(dst + c) = *reinterpret_cast<unsigned*>(&p);
            }
        }
    }
}

// ----------------------------- down GEMM ------------------------------------
__global__ __launch_bounds__(256, 2) void d_gemm_kernel() {
    int tile = blockIdx.y;
    if (tile >= g_ntiles) return;
    int e = g_tile_e[tile];
    int rowbase = tile * 128;
    int n0 = blockIdx.x * 128;
    int tid = threadIdx.x;

    extern __shared__ __nv_bfloat16 smem[];
    uint32_t smBase = (uint32_t)__cvta_generic_to_shared(smem);

    auto loadStage = [&](int s) {
        uint32_t buf = smBase + (uint32_t)(s % 3) * (D_STG * 2);
        int k0 = s * BK;
#pragma unroll
        for (int it = 0; it < 4; it++) {               // A
            int c = tid + it * 256;
            int row = c >> 3, ch = c & 7;
            uint32_t d = buf + (uint32_t)(row*64 + ((ch ^ (row & 7)) * 8)) * 2;
            cpa16(d, g_A2 + (size_t)(rowbase + row)*DIM + k0 + ch*8);
        }
#pragma unroll
        for (int it = 0; it < 4; it++) {               // B
            int c = tid + it * 256;
            int row = c >> 3, ch = c & 7;
            uint32_t d = buf + (uint32_t)(8192 + row*64 + ((ch ^ (row & 7)) * 8)) * 2;
            cpa16(d, g_Wdb + ((size_t)e*DIM + n0 + row)*DIM + k0 + ch*8);
        }
    };

    float acc[2][8][4];
#pragma unroll
    for (int mt = 0; mt < 2; mt++)
#pragma unroll
        for (int nt = 0; nt < 8; nt++)
#pragma unroll
            for (int i = 0; i < 4; i++) acc[mt][nt][i] = 0.f;

    int lane = tid & 31, warp = tid >> 5;
    int wm = warp & 3, wn = warp >> 2;    // warp tile 32 x 64

    loadStage(0); CP_COMMIT;
    loadStage(1); CP_COMMIT;

    for (int s = 0; s < NS; s++) {
        cp_wait<1>();
        __syncthreads();
        if (s + 2 < NS) loadStage(s + 2);
        CP_COMMIT;

        uint32_t buf = smBase + (uint32_t)(s % 3) * (D_STG * 2);
#pragma unroll
        for (int kk = 0; kk < BK; kk += 16) {
            int kh = kk + ((lane >> 4) << 3);
            unsigned af[2][4];
#pragma unroll
            for (int mt = 0; mt < 2; mt++) {
                int arow = wm*32 + mt*16 + (lane & 15);
                uint32_t a = buf + (uint32_t)(arow*64 +
                              (((kh >> 3) ^ (arow & 7)) << 3)) * 2;
                ldsm4(af[mt][0], af[mt][1], af[mt][2], af[mt][3], a);
            }
            unsigned bq[8][2];
#pragma unroll
            for (int p = 0; p < 4; p++) {
                int brow = wn*64 + p*16 + (lane & 15);
                uint32_t b = buf + (uint32_t)(8192 + brow*64 +
                              (((kh >> 3) ^ (brow & 7)) << 3)) * 2;
                unsigned q0, q1, q2, q3;
                ldsm4(q0, q1, q2, q3, b);
                bq[2*p][0]   = q0; bq[2*p][1]   = q2;
                bq[2*p+1][0] = q1; bq[2*p+1][1] = q3;
            }
#pragma unroll
            for (int mt = 0; mt < 2; mt++)
#pragma unroll
                for (int nt = 0; nt < 8; nt++)
                    mma16816(acc[mt][nt], af[mt], bq[nt]);
        }
    }

    int g = lane >> 2, t4 = lane & 3;
#pragma unroll
    for (int mt = 0; mt < 2; mt++) {
#pragma unroll
        for (int hrow = 0; hrow < 2; hrow++) {
            int r = wm*32 + mt*16 + g + hrow*8;
            __nv_bfloat16* dst = g_D + (size_t)(rowbase + r)*DIM + n0;
#pragma unroll
            for (int nt = 0; nt < 8; nt++) {
                int c = wn*64 + nt*8 + 2*t4;
                __nv_bfloat162 p = __floats2bfloat162_rn(
                    acc[mt][nt][hrow*2], acc[mt][nt][hrow*2 + 1]);
                *(unsigned*)(dst + c) = *reinterpret_cast<unsigned*>(&p);
            }
        }
    }
}

// --------------------------- combine (+loss) --------------------------------
__global__ void combine_kernel(const float* __restrict__ Xh,
                               const float* __restrict__ alpha,
                               float* __restrict__ out, int lossidx) {
    int t = blockIdx.x;
    if (t == 0 && threadIdx.x == 0) {
        float s = 0.f;
        for (int e = 0; e < NE; e++) s += g_importance[e] * (float)g_counts[e];
        float lb = AUXC * ((float)NE * s / ((float)T_TOK * (float)T_TOK));
        float z  = ZC * (g_zsum / (float)T_TOK);
        out[lossidx] = lb + z;
    }
    int e0 = g_re[2*t], e1 = g_re[2*t+1];
    size_t r0 = (size_t)(g_offsets[e0] + g_rs[2*t]) * DIM;
    size_t r1 = (size_t)(g_offsets[e1] + g_rs[2*t+1]) * DIM;
    float al = alpha[0];
    float w0 = g_rg[2*t] * al, w1 = g_rg[2*t+1] * al;
    const float4* h4 = (const float4*)(Xh + (size_t)t * DIM);
    const __nv_bfloat16* d0 = g_D + r0;
    const __nv_bfloat16* d1 = g_D + r1;
    float4* o4 = (float4*)(out + (size_t)t * DIM);
    for (int i = threadIdx.x; i < DIM/4; i += blockDim.x) {
        float4 h = h4[i];
        uint2 a2 = *(const uint2*)(d0 + i*4);
        uint2 b2 = *(const uint2*)(d1 + i*4);
        float2 a0 = __bfloat1622float2(*reinterpret_cast<__nv_bfloat162*>(&a2.x));
        float2 a1 = __bfloat1622float2(*reinterpret_cast<__nv_bfloat162*>(&a2.y));
        float2 b0 = __bfloat1622float2(*reinterpret_cast<__nv_bfloat162*>(&b2.x));
        float2 b1 = __bfloat1622float2(*reinterpret_cast<__nv_bfloat162*>(&b2.y));
        float4 r;
        r.x = h.x + w0*a0.x + w1*b0.x;
        r.y = h.y + w0*a0.y + w1*b0.y;
        r.z = h.z + w0*a1.x + w1*b1.x;
        r.w = h.w + w0*a1.y + w1*b1.y;
        o4[i] = r;
    }
}

// ------------------------------- launcher -----------------------------------
extern "C" void kernel_launch(void* const* d_in, const int* in_sizes, int n_in,
                              void* d_out, int out_size) {
    const float* X      = (const float*)d_in[0];
    const float* Wg     = (const float*)d_in[1];
    const float* gate_w = (const float*)d_in[2];
    const float* gate_A = (const float*)d_in[3];
    const float* gate_B = (const float*)d_in[4];
    const float* up_w   = (const float*)d_in[5];
    const float* up_A   = (const float*)d_in[6];
    const float* up_B   = (const float*)d_in[7];
    const float* down_w = (const float*)d_in[8];
    const float* down_A = (const float*)d_in[9];
    const float* down_B = (const float*)d_in[10];
    const float* alpha  = (const float*)d_in[11];
    float* out = (float*)d_out;

    cudaFuncSetAttribute(gu_gemm_kernel, cudaFuncAttributeMaxDynamicSharedMemorySize, GU_SMEM);
    cudaFuncSetAttribute(d_gemm_kernel,  cudaFuncAttributeMaxDynamicSharedMemorySize, D_SMEM);

    __nv_bfloat16 *dWgb, *dWub, *dWdb;
    cudaGetSymbolAddress((void**)&dWgb, g_Wgb);
    cudaGetSymbolAddress((void**)&dWub, g_Wub);
    cudaGetSymbolAddress((void**)&dWdb, g_Wdb);

    // Launch order: gu_gemm is our index 3 (= ncu capture slot, harness +2).
    dim3 fgrid(DIM/128, DIM/64, 3*NE);
    fold_kernel<<<fgrid, 256>>>(gate_w, gate_A, gate_B,         // 0 (+init)
                                up_w,   up_A,   up_B,
                                down_w, down_A, down_B,
                                dWgb, dWub, dWdb);
    router_kernel<<<T_TOK/8, 256>>>(X, Wg);                     // 1
    gather_kernel<<<PADROWS, 256>>>(X);                         // 2 (+offsets)

    dim3 gugrid(DIM/64, MAXTILES);
    gu_gemm_kernel<<<gugrid, 256, GU_SMEM>>>();                 // 3  <- profiled

    dim3 dgrid(DIM/128, MAXTILES);
    d_gemm_kernel<<<dgrid, 256, D_SMEM>>>();                    // 4

    combine_kernel<<<T_TOK, 256>>>(X, alpha, out, out_size - 1);// 5 (+loss)
}

// round 13
// speedup vs baseline: 1.0130x; 1.0130x over previous
#include <cuda_runtime.h>
#include <cuda_bf16.h>
#include <math.h>
#include <stdint.h>

// ---------------------------------------------------------------------------
// MoE + LoRA forward, routed top-2/8. Legacy mma.sync bf16 tensor path.
// Round 13: router merged into fold launch (z-slices 0-1, overlapped);
// routing-state re-init moved to combine tail (valid across graph replays).
// GEMMs bit-identical to the 1397us baseline. 5 launches; d_gemm profiled.
// ---------------------------------------------------------------------------

#define DIM    2048
#define T_TOK  8192
#define NE     8
#define NR     16
#define NROWS  (T_TOK*2)
#define PADROWS (NROWS + NE*128)      // per-expert counts padded to 128
#define MAXTILES (PADROWS/128)        // 136
#define SCALING 2.0f
#define AUXC   0.01f
#define ZC     0.001f

#define BK 64
#define NS 32                              // 2048 / 64 K-stages
#define GU_STG (128*64 + 64*64 + 64*64)    // halves/stage: A + Bg + Bu
#define D_STG  (128*64 + 128*64)           // halves/stage: A + B
#define GU_SMEM (3*GU_STG*2)               // 98304 B
#define D_SMEM  (3*D_STG*2)                // 98304 B

// ------------------------- scratch (device globals) ------------------------
// NOTE: zero-initialized at module load; combine_kernel re-zeroes the routing
// state at the end of every call, so each graph replay starts clean.
__device__ int   g_counts[NE];
__device__ int   g_offsets[NE+1];     // padded cumulative offsets
__device__ int   g_tile_e[MAXTILES];
__device__ int   g_ntiles;
__device__ float g_importance[NE];
__device__ float g_zsum;
__device__ int   g_tok[NE*T_TOK];
__device__ int   g_re[NROWS];
__device__ int   g_rs[NROWS];
__device__ float g_rg[NROWS];

__device__ __nv_bfloat16 g_Xg[(size_t)PADROWS*DIM];    // gathered bf16 X rows
__device__ __nv_bfloat16 g_Wgb[(size_t)NE*DIM*DIM];    // folded bf16 weights
__device__ __nv_bfloat16 g_Wub[(size_t)NE*DIM*DIM];
__device__ __nv_bfloat16 g_Wdb[(size_t)NE*DIM*DIM];

__device__ __nv_bfloat16 g_A2[(size_t)PADROWS*DIM];    // silu(g)*u
__device__ __nv_bfloat16 g_D[(size_t)PADROWS*DIM];     // down output (bf16)

// ------------------------------- helpers -----------------------------------
__device__ __forceinline__ uint2 cvt4(float4 v) {
    __nv_bfloat162 lo = __floats2bfloat162_rn(v.x, v.y);
    __nv_bfloat162 hi = __floats2bfloat162_rn(v.z, v.w);
    uint2 r;
    r.x = *reinterpret_cast<unsigned*>(&lo);
    r.y = *reinterpret_cast<unsigned*>(&hi);
    return r;
}

__device__ __forceinline__ void mma16816(float* d, const unsigned* a, const unsigned* b) {
    asm volatile(
        "mma.sync.aligned.m16n8k16.row.col.f32.bf16.bf16.f32 "
        "{%0,%1,%2,%3}, {%4,%5,%6,%7}, {%8,%9}, {%0,%1,%2,%3};\n"
        : "+f"(d[0]), "+f"(d[1]), "+f"(d[2]), "+f"(d[3])
        : "r"(a[0]), "r"(a[1]), "r"(a[2]), "r"(a[3]), "r"(b[0]), "r"(b[1]));
}

__device__ __forceinline__ void ldsm4(unsigned &r0, unsigned &r1, unsigned &r2,
                                      unsigned &r3, uint32_t addr) {
    asm volatile("ldmatrix.sync.aligned.m8n8.x4.shared.b16 {%0,%1,%2,%3}, [%4];\n"
                 : "=r"(r0), "=r"(r1), "=r"(r2), "=r"(r3) : "r"(addr));
}

__device__ __forceinline__ void cpa16(uint32_t dst, const void* src) {
    asm volatile("cp.async.cg.shared.global [%0], [%1], 16;\n" :: "r"(dst), "l"(src));
}
#define CP_COMMIT asm volatile("cp.async.commit_group;\n")
template<int N> __device__ __forceinline__ void cp_wait() {
    asm volatile("cp.async.wait_group %0;\n" :: "n"(N));
}

// packed fp32x2 helpers (fma.rn.f32x2 assembles on this toolchain)
__device__ __forceinline__ void fma2(uint64_t& d, uint64_t a, uint64_t b) {
    asm("fma.rn.f32x2 %0, %1, %2, %3;" : "=l"(d) : "l"(a), "l"(b), "l"(d));
}
__device__ __forceinline__ uint64_t packf2(float lo, float hi) {
    uint64_t r;
    asm("mov.b64 %0, {%1, %2};" : "=l"(r) : "f"(lo), "f"(hi));
    return r;
}
__device__ __forceinline__ void unpackf2(uint64_t p, float& lo, float& hi) {
    asm("mov.b64 {%0, %1}, %2;" : "=f"(lo), "=f"(hi) : "l"(p));
}

// ------------- fold + router fused launch (z 0-1: router, 2-25: fold) -------
// fold: W' = bf16(W + SCALING * B @ A). router: top-2 gating + slot assign.
// Router z-slices are scheduled first so their DRAM reads overlap fold body.
// Routing state (g_counts/importance/zsum) is pre-zeroed by the previous
// combine call (or module load on the first call).
__global__ __launch_bounds__(256) void fold_router_kernel(
        const float* __restrict__ X,   const float* __restrict__ Wgate,
        const float* __restrict__ Wg_, const float* __restrict__ Ag_,
        const float* __restrict__ Bg_,
        const float* __restrict__ Wu_, const float* __restrict__ Au_,
        const float* __restrict__ Bu_,
        const float* __restrict__ Wd_, const float* __restrict__ Ad_,
        const float* __restrict__ Bd_,
        __nv_bfloat16* __restrict__ Og_, __nv_bfloat16* __restrict__ Ou_,
        __nv_bfloat16* __restrict__ Od_) {
    int z = blockIdx.z;
    if (z < 2) {
        // ---------------- router path ----------------
        int rblk = z * 512 + blockIdx.y * 16 + blockIdx.x;   // 0..1023
        int warp = threadIdx.x >> 5, lane = threadIdx.x & 31;
        int t = rblk * 8 + warp;
        if (t >= T_TOK) return;
        const float4* xr = (const float4*)(X + (size_t)t * DIM);
        float acc[NE];
#pragma unroll
        for (int e = 0; e < NE; e++) acc[e] = 0.f;
        for (int i = lane; i < DIM/4; i += 32) {
            float4 xv = xr[i];
#pragma unroll
            for (int e = 0; e < NE; e++) {
                float4 w = ((const float4*)(Wgate + (size_t)e * DIM))[i];
                acc[e] += xv.x*w.x + xv.y*w.y + xv.z*w.z + xv.w*w.w;
            }
        }
#pragma unroll
        for (int e = 0; e < NE; e++)
#pragma unroll
            for (int o = 16; o > 0; o >>= 1)
                acc[e] += __shfl_xor_sync(0xffffffffu, acc[e], o);

        if (lane == 0) {
            int e0 = 0;
#pragma unroll
            for (int e = 1; e < NE; e++) if (acc[e] > acc[e0]) e0 = e;
            int e1 = (e0 == 0) ? 1 : 0;
#pragma unroll
            for (int e = 0; e < NE; e++)
                if (e != e0 && acc[e] > acc[e1]) e1 = e;

            float m = acc[e0];
            float s = 0.f;
#pragma unroll
            for (int e = 0; e < NE; e++) s += expf(acc[e] - m);
            float lse = logf(s) + m;
            atomicAdd(&g_zsum, lse * lse);

            float d = expf(acc[e1] - acc[e0]);
            float p0 = 1.f / (1.f + d);
            float p1 = d / (1.f + d);

            int s0 = atomicAdd(&g_counts[e0], 1);
            int s1 = atomicAdd(&g_counts[e1], 1);
            g_tok[e0*T_TOK + s0] = t;
            g_tok[e1*T_TOK + s1] = t;
            atomicAdd(&g_importance[e0], p0);
            atomicAdd(&g_importance[e1], p1);
            g_re[2*t] = e0;  g_rs[2*t] = s0;  g_rg[2*t] = p0;
            g_re[2*t+1] = e1; g_rs[2*t+1] = s1; g_rg[2*t+1] = p1;
        }
        return;
    }

    // ---------------- fold path ----------------
    int zz = z - 2;
    int wsel = zz >> 3;          // 0=gate, 1=up, 2=down
    int e = zz & 7;
    const float* W = (wsel == 0) ? Wg_ : (wsel == 1) ? Wu_ : Wd_;
    const float* A = (wsel == 0) ? Ag_ : (wsel == 1) ? Au_ : Ad_;
    const float* B = (wsel == 0) ? Bg_ : (wsel == 1) ? Bu_ : Bd_;
    __nv_bfloat16* out = (wsel == 0) ? Og_ : (wsel == 1) ? Ou_ : Od_;

    int tid = threadIdx.x;
    int n  = blockIdx.y * 64 + (tid >> 2);
    int k0 = blockIdx.x * 128;

    __shared__ float As[NR][128];
#pragma unroll
    for (int i = 0; i < 8; i++) {
        int idx = tid + i * 256;
        As[idx >> 7][idx & 127] = A[((size_t)e*NR + (idx >> 7))*DIM + k0 + (idx & 127)];
    }
    __syncthreads();

    uint64_t Brp[NR];
    {
        const float4* b4 = (const float4*)(B + ((size_t)e*DIM + n)*NR);
#pragma unroll
        for (int q = 0; q < 4; q++) {
            float4 v = b4[q];
            Brp[q*4+0] = packf2(SCALING * v.x, SCALING * v.x);
            Brp[q*4+1] = packf2(SCALING * v.y, SCALING * v.y);
            Brp[q*4+2] = packf2(SCALING * v.z, SCALING * v.z);
            Brp[q*4+3] = packf2(SCALING * v.w, SCALING * v.w);
        }
    }

    const float* Wrow = W + ((size_t)e*DIM + n)*DIM + k0;
    __nv_bfloat16* Orow = out + ((size_t)e*DIM + n)*DIM + k0;
#pragma unroll
    for (int q = 0; q < 8; q++) {
        int k = q*16 + (tid & 3)*4;    // interleaved: conflict-free smem banks
        float4 w = *(const float4*)(Wrow + k);
        uint64_t p01 = packf2(w.x, w.y);
        uint64_t p23 = packf2(w.z, w.w);
#pragma unroll
        for (int r = 0; r < NR; r++) {
            uint64_t a01 = *(const uint64_t*)&As[r][k];
            uint64_t a23 = *(const uint64_t*)&As[r][k+2];
            fma2(p01, Brp[r], a01);
            fma2(p23, Brp[r], a23);
        }
        float f0, f1, f2, f3;
        unpackf2(p01, f0, f1);
        unpackf2(p23, f2, f3);
        __nv_bfloat162 lo = __floats2bfloat162_rn(f0, f1);
        __nv_bfloat162 hi = __floats2bfloat162_rn(f2, f3);
        uint2 o;
        o.x = *reinterpret_cast<unsigned*>(&lo);
        o.y = *reinterpret_cast<unsigned*>(&hi);
        *(uint2*)(Orow + k) = o;
    }
}

// gather(+offsets): derive padded offsets from g_counts per block; block 0
// publishes g_offsets / g_tile_e / g_ntiles for downstream kernels.
__global__ void gather_kernel(const float* __restrict__ X) {
    int offs[NE+1];
    int o = 0;
#pragma unroll
    for (int e = 0; e < NE; e++) {
        offs[e] = o;
        o += ((g_counts[e] + 127) >> 7) << 7;
    }
    offs[NE] = o;

    if (blockIdx.x == 0) {
        int t = threadIdx.x;
        if (t <= NE) g_offsets[t] = offs[t];
        if (t == 0) g_ntiles = o >> 7;
        if (t < MAXTILES && t < (o >> 7)) {
            int te = 0;
#pragma unroll
            for (int e = 0; e < NE; e++)
                if (t*128 >= offs[e]) te = e;
            g_tile_e[t] = te;
        }
    }

    int row = blockIdx.x;
    if (row >= o) return;
    int e = 0;
#pragma unroll
    for (int q = 0; q < NE; q++)
        if (row >= offs[q]) e = q;
    int slot = row - offs[e];
    __nv_bfloat16* dst = g_Xg + (size_t)row * DIM;
    if (slot < g_counts[e]) {
        const float4* src = (const float4*)(X + (size_t)g_tok[e*T_TOK + slot] * DIM);
        for (int i = threadIdx.x; i < DIM/4; i += blockDim.x)
            *(uint2*)(dst + i*4) = cvt4(src[i]);
    } else {
        for (int i = threadIdx.x; i < DIM/4; i += blockDim.x)
            *(uint2*)(dst + i*4) = make_uint2(0u, 0u);
    }
}

// ----------------------- fused gate+up GEMM (mma.sync) ----------------------
// C_gate[128x64] and C_up[128x64] for the same (tile, n0); A tile shared.
__global__ __launch_bounds__(256, 2) void gu_gemm_kernel() {
    int tile = blockIdx.y;
    if (tile >= g_ntiles) return;
    int e = g_tile_e[tile];
    int rowbase = tile * 128;
    int n0 = blockIdx.x * 64;
    int tid = threadIdx.x;

    extern __shared__ __nv_bfloat16 smem[];
    uint32_t smBase = (uint32_t)__cvta_generic_to_shared(smem);

    auto loadStage = [&](int s) {
        uint32_t buf = smBase + (uint32_t)(s % 3) * (GU_STG * 2);
        int k0 = s * BK;
#pragma unroll
        for (int it = 0; it < 4; it++) {           // A: 1024 x 16B
            int c = tid + it * 256;
            int row = c >> 3, ch = c & 7;
            uint32_t d = buf + (uint32_t)(row*64 + ((ch ^ (row & 7)) * 8)) * 2;
            cpa16(d, g_Xg + (size_t)(rowbase + row)*DIM + k0 + ch*8);
        }
#pragma unroll
        for (int it = 0; it < 2; it++) {           // Bg: 512 x 16B
            int c = tid + it * 256;
            int row = c >> 3, ch = c & 7;
            uint32_t d = buf + (uint32_t)(8192 + row*64 + ((ch ^ (row & 7)) * 8)) * 2;
            cpa16(d, g_Wgb + ((size_t)e*DIM + n0 + row)*DIM + k0 + ch*8);
        }
#pragma unroll
        for (int it = 0; it < 2; it++) {           // Bu
            int c = tid + it * 256;
            int row = c >> 3, ch = c & 7;
            uint32_t d = buf + (uint32_t)(12288 + row*64 + ((ch ^ (row & 7)) * 8)) * 2;
            cpa16(d, g_Wub + ((size_t)e*DIM + n0 + row)*DIM + k0 + ch*8);
        }
    };

    float ag[2][4][4], au[2][4][4];
#pragma unroll
    for (int mt = 0; mt < 2; mt++)
#pragma unroll
        for (int nt = 0; nt < 4; nt++)
#pragma unroll
            for (int i = 0; i < 4; i++) { ag[mt][nt][i] = 0.f; au[mt][nt][i] = 0.f; }

    int lane = tid & 31, warp = tid >> 5;
    int wm = warp & 3, wn = warp >> 2;    // 4x2 warps; 32 rows x 32 cols each

    loadStage(0); CP_COMMIT;
    loadStage(1); CP_COMMIT;

    for (int s = 0; s < NS; s++) {
        cp_wait<1>();
        __syncthreads();
        if (s + 2 < NS) loadStage(s + 2);
        CP_COMMIT;

        uint32_t buf = smBase + (uint32_t)(s % 3) * (GU_STG * 2);
#pragma unroll
        for (int kk = 0; kk < BK; kk += 16) {
            int kh = kk + ((lane >> 4) << 3);
            unsigned af[2][4];
#pragma unroll
            for (int mt = 0; mt < 2; mt++) {
                int arow = wm*32 + mt*16 + (lane & 15);
                uint32_t a = buf + (uint32_t)(arow*64 +
                              (((kh >> 3) ^ (arow & 7)) << 3)) * 2;
                ldsm4(af[mt][0], af[mt][1], af[mt][2], af[mt][3], a);
            }
            unsigned bg[4][2];
#pragma unroll
            for (int p = 0; p < 2; p++) {
                int brow = wn*32 + p*16 + (lane & 15);
                uint32_t b = buf + (uint32_t)(8192 + brow*64 +
                              (((kh >> 3) ^ (brow & 7)) << 3)) * 2;
                unsigned q0, q1, q2, q3;
                ldsm4(q0, q1, q2, q3, b);
                bg[2*p][0] = q0; bg[2*p][1] = q2;
                bg[2*p+1][0] = q1; bg[2*p+1][1] = q3;
            }
#pragma unroll
            for (int mt = 0; mt < 2; mt++)
#pragma unroll
                for (int nt = 0; nt < 4; nt++)
                    mma16816(ag[mt][nt], af[mt], bg[nt]);
            unsigned bu[4][2];
#pragma unroll
            for (int p = 0; p < 2; p++) {
                int brow = wn*32 + p*16 + (lane & 15);
                uint32_t b = buf + (uint32_t)(12288 + brow*64 +
                              (((kh >> 3) ^ (brow & 7)) << 3)) * 2;
                unsigned q0, q1, q2, q3;
                ldsm4(q0, q1, q2, q3, b);
                bu[2*p][0] = q0; bu[2*p][1] = q2;
                bu[2*p+1][0] = q1; bu[2*p+1][1] = q3;
            }
#pragma unroll
            for (int mt = 0; mt < 2; mt++)
#pragma unroll
                for (int nt = 0; nt < 4; nt++)
                    mma16816(au[mt][nt], af[mt], bu[nt]);
        }
    }

    // epilogue: a = silu(g) * u -> g_A2 bf16
    int g = lane >> 2, t4 = lane & 3;
#pragma unroll
    for (int mt = 0; mt < 2; mt++) {
#pragma unroll
        for (int hrow = 0; hrow < 2; hrow++) {
            int r = wm*32 + mt*16 + g + hrow*8;
            __nv_bfloat16* dst = g_A2 + (size_t)(rowbase + r)*DIM + n0;
#pragma unroll
            for (int nt = 0; nt < 4; nt++) {
                int c = wn*32 + nt*8 + 2*t4;
                float g0 = ag[mt][nt][hrow*2 + 0];
                float g1 = ag[mt][nt][hrow*2 + 1];
                float u0 = au[mt][nt][hrow*2 + 0];
                float u1 = au[mt][nt][hrow*2 + 1];
                float a0 = g0 / (1.f + expf(-g0)) * u0;
                float a1 = g1 / (1.f + expf(-g1)) * u1;
                __nv_bfloat162 p = __floats2bfloat162_rn(a0, a1);
                *(unsigned*)(dst + c) = *reinterpret_cast<unsigned*>(&p);
            }
        }
    }
}

// ----------------------------- down GEMM ------------------------------------
__global__ __launch_bounds__(256, 2) void d_gemm_kernel() {
    int tile = blockIdx.y;
    if (tile >= g_ntiles) return;
    int e = g_tile_e[tile];
    int rowbase = tile * 128;
    int n0 = blockIdx.x * 128;
    int tid = threadIdx.x;

    extern __shared__ __nv_bfloat16 smem[];
    uint32_t smBase = (uint32_t)__cvta_generic_to_shared(smem);

    auto loadStage = [&](int s) {
        uint32_t buf = smBase + (uint32_t)(s % 3) * (D_STG * 2);
        int k0 = s * BK;
#pragma unroll
        for (int it = 0; it < 4; it++) {               // A
            int c = tid + it * 256;
            int row = c >> 3, ch = c & 7;
            uint32_t d = buf + (uint32_t)(row*64 + ((ch ^ (row & 7)) * 8)) * 2;
            cpa16(d, g_A2 + (size_t)(rowbase + row)*DIM + k0 + ch*8);
        }
#pragma unroll
        for (int it = 0; it < 4; it++) {               // B
            int c = tid + it * 256;
            int row = c >> 3, ch = c & 7;
            uint32_t d = buf + (uint32_t)(8192 + row*64 + ((ch ^ (row & 7)) * 8)) * 2;
            cpa16(d, g_Wdb + ((size_t)e*DIM + n0 + row)*DIM + k0 + ch*8);
        }
    };

    float acc[2][8][4];
#pragma unroll
    for (int mt = 0; mt < 2; mt++)
#pragma unroll
        for (int nt = 0; nt < 8; nt++)
#pragma unroll
            for (int i = 0; i < 4; i++) acc[mt][nt][i] = 0.f;

    int lane = tid & 31, warp = tid >> 5;
    int wm = warp & 3, wn = warp >> 2;    // warp tile 32 x 64

    loadStage(0); CP_COMMIT;
    loadStage(1); CP_COMMIT;

    for (int s = 0; s < NS; s++) {
        cp_wait<1>();
        __syncthreads();
        if (s + 2 < NS) loadStage(s + 2);
        CP_COMMIT;

        uint32_t buf = smBase + (uint32_t)(s % 3) * (D_STG * 2);
#pragma unroll
        for (int kk = 0; kk < BK; kk += 16) {
            int kh = kk + ((lane >> 4) << 3);
            unsigned af[2][4];
#pragma unroll
            for (int mt = 0; mt < 2; mt++) {
                int arow = wm*32 + mt*16 + (lane & 15);
                uint32_t a = buf + (uint32_t)(arow*64 +
                              (((kh >> 3) ^ (arow & 7)) << 3)) * 2;
                ldsm4(af[mt][0], af[mt][1], af[mt][2], af[mt][3], a);
            }
            unsigned bq[8][2];
#pragma unroll
            for (int p = 0; p < 4; p++) {
                int brow = wn*64 + p*16 + (lane & 15);
                uint32_t b = buf + (uint32_t)(8192 + brow*64 +
                              (((kh >> 3) ^ (brow & 7)) << 3)) * 2;
                unsigned q0, q1, q2, q3;
                ldsm4(q0, q1, q2, q3, b);
                bq[2*p][0]   = q0; bq[2*p][1]   = q2;
                bq[2*p+1][0] = q1; bq[2*p+1][1] = q3;
            }
#pragma unroll
            for (int mt = 0; mt < 2; mt++)
#pragma unroll
                for (int nt = 0; nt < 8; nt++)
                    mma16816(acc[mt][nt], af[mt], bq[nt]);
        }
    }

    int g = lane >> 2, t4 = lane & 3;
#pragma unroll
    for (int mt = 0; mt < 2; mt++) {
#pragma unroll
        for (int hrow = 0; hrow < 2; hrow++) {
            int r = wm*32 + mt*16 + g + hrow*8;
            __nv_bfloat16* dst = g_D + (size_t)(rowbase + r)*DIM + n0;
#pragma unroll
            for (int nt = 0; nt < 8; nt++) {
                int c = wn*64 + nt*8 + 2*t4;
                __nv_bfloat162 p = __floats2bfloat162_rn(
                    acc[mt][nt][hrow*2], acc[mt][nt][hrow*2 + 1]);
                *(unsigned*)(dst + c) = *reinterpret_cast<unsigned*>(&p);
            }
        }
    }
}

// ----------------- combine (+loss, +re-init for next replay) ----------------
__global__ void combine_kernel(const float* __restrict__ Xh,
                               const float* __restrict__ alpha,
                               float* __restrict__ out, int lossidx) {
    int t = blockIdx.x;
    if (t == 0 && threadIdx.x == 0) {
        float s = 0.f;
        for (int e = 0; e < NE; e++) s += g_importance[e] * (float)g_counts[e];
        float lb = AUXC * ((float)NE * s / ((float)T_TOK * (float)T_TOK));
        float z  = ZC * (g_zsum / (float)T_TOK);
        out[lossidx] = lb + z;
        // re-zero routing state for the next graph replay (after all reads:
        // only this thread reads g_counts/g_importance/g_zsum).
        for (int e = 0; e < NE; e++) { g_counts[e] = 0; g_importance[e] = 0.f; }
        g_zsum = 0.f;
    }
    int e0 = g_re[2*t], e1 = g_re[2*t+1];
    size_t r0 = (size_t)(g_offsets[e0] + g_rs[2*t]) * DIM;
    size_t r1 = (size_t)(g_offsets[e1] + g_rs[2*t+1]) * DIM;
    float al = alpha[0];
    float w0 = g_rg[2*t] * al, w1 = g_rg[2*t+1] * al;
    const float4* h4 = (const float4*)(Xh + (size_t)t * DIM);
    const __nv_bfloat16* d0 = g_D + r0;
    const __nv_bfloat16* d1 = g_D + r1;
    float4* o4 = (float4*)(out + (size_t)t * DIM);
    for (int i = threadIdx.x; i < DIM/4; i += blockDim.x) {
        float4 h = h4[i];
        uint2 a2 = *(const uint2*)(d0 + i*4);
        uint2 b2 = *(const uint2*)(d1 + i*4);
        float2 a0 = __bfloat1622float2(*reinterpret_cast<__nv_bfloat162*>(&a2.x));
        float2 a1 = __bfloat1622float2(*reinterpret_cast<__nv_bfloat162*>(&a2.y));
        float2 b0 = __bfloat1622float2(*reinterpret_cast<__nv_bfloat162*>(&b2.x));
        float2 b1 = __bfloat1622float2(*reinterpret_cast<__nv_bfloat162*>(&b2.y));
        float4 r;
        r.x = h.x + w0*a0.x + w1*b0.x;
        r.y = h.y + w0*a0.y + w1*b0.y;
        r.z = h.z + w0*a1.x + w1*b1.x;
        r.w = h.w + w0*a1.y + w1*b1.y;
        o4[i] = r;
    }
}

// ------------------------------- launcher -----------------------------------
extern "C" void kernel_launch(void* const* d_in, const int* in_sizes, int n_in,
                              void* d_out, int out_size) {
    const float* X      = (const float*)d_in[0];
    const float* Wg     = (const float*)d_in[1];
    const float* gate_w = (const float*)d_in[2];
    const float* gate_A = (const float*)d_in[3];
    const float* gate_B = (const float*)d_in[4];
    const float* up_w   = (const float*)d_in[5];
    const float* up_A   = (const float*)d_in[6];
    const float* up_B   = (const float*)d_in[7];
    const float* down_w = (const float*)d_in[8];
    const float* down_A = (const float*)d_in[9];
    const float* down_B = (const float*)d_in[10];
    const float* alpha  = (const float*)d_in[11];
    float* out = (float*)d_out;

    cudaFuncSetAttribute(gu_gemm_kernel, cudaFuncAttributeMaxDynamicSharedMemorySize, GU_SMEM);
    cudaFuncSetAttribute(d_gemm_kernel,  cudaFuncAttributeMaxDynamicSharedMemorySize, D_SMEM);

    __nv_bfloat16 *dWgb, *dWub, *dWdb;
    cudaGetSymbolAddress((void**)&dWgb, g_Wgb);
    cudaGetSymbolAddress((void**)&dWub, g_Wub);
    cudaGetSymbolAddress((void**)&dWdb, g_Wdb);

    // 0: fold + router (router = z 0-1, overlapped with fold z 2-25)
    dim3 frgrid(DIM/128, DIM/64, 3*NE + 2);
    fold_router_kernel<<<frgrid, 256>>>(X, Wg,
                                        gate_w, gate_A, gate_B,
                                        up_w,   up_A,   up_B,
                                        down_w, down_A, down_B,
                                        dWgb, dWub, dWdb);
    // 1: gather (+offsets)
    gather_kernel<<<PADROWS, 256>>>(X);

    // 2: fused gate+up GEMM -> g_A2
    dim3 gugrid(DIM/64, MAXTILES);
    gu_gemm_kernel<<<gugrid, 256, GU_SMEM>>>();

    // 3: down GEMM -> g_D   (<- ncu capture slot: harness +2)
    dim3 dgrid(DIM/128, MAXTILES);
    d_gemm_kernel<<<dgrid, 256, D_SMEM>>>();

    // 4: combine (+loss, +re-init)
    combine_kernel<<<T_TOK, 256>>>(X, alpha, out, out_size - 1);
}

// round 14
// speedup vs baseline: 1.0183x; 1.0053x over previous
#include <cuda_runtime.h>
#include <cuda_bf16.h>
#include <math.h>
#include <stdint.h>

// ---------------------------------------------------------------------------
// MoE + LoRA forward, routed top-2/8. Legacy mma.sync bf16 tensor path.
// Round 14: gather kernel eliminated (dense X->bf16 conversion folded into the
// fold launch; gu GEMM gathers A rows via smem toks[] + cp.async zero-fill).
// 4 launches: fold(+router+xconv), gu_gemm, d_gemm(+publish offsets), combine.
// GEMM mainloops bit-identical to the 1392us baseline (structural ceiling).
// ---------------------------------------------------------------------------

#define DIM    2048
#define T_TOK  8192
#define NE     8
#define NR     16
#define NROWS  (T_TOK*2)
#define PADROWS (NROWS + NE*128)      // per-expert counts padded to 128
#define MAXTILES (PADROWS/128)        // 136
#define SCALING 2.0f
#define AUXC   0.01f
#define ZC     0.001f

#define BK 64
#define NS 32                              // 2048 / 64 K-stages
#define GU_STG (128*64 + 64*64 + 64*64)    // halves/stage: A + Bg + Bu
#define D_STG  (128*64 + 128*64)           // halves/stage: A + B
#define GU_SMEM (3*GU_STG*2 + 512)         // + toks[128]
#define D_SMEM  (3*D_STG*2)                // 98304 B

// ------------------------- scratch (device globals) ------------------------
// Zero-initialized at module load; combine re-zeroes routing state each call.
__device__ int   g_counts[NE];
__device__ int   g_offsets[NE+1];     // published by d_gemm CTA0 for combine
__device__ float g_importance[NE];
__device__ float g_zsum;
__device__ int   g_tok[NE*T_TOK];
__device__ int   g_re[NROWS];
__device__ int   g_rs[NROWS];
__device__ float g_rg[NROWS];

__device__ __nv_bfloat16 g_Xb[(size_t)T_TOK*DIM];      // dense bf16 X
__device__ __nv_bfloat16 g_Wgb[(size_t)NE*DIM*DIM];    // folded bf16 weights
__device__ __nv_bfloat16 g_Wub[(size_t)NE*DIM*DIM];
__device__ __nv_bfloat16 g_Wdb[(size_t)NE*DIM*DIM];

__device__ __nv_bfloat16 g_A2[(size_t)PADROWS*DIM];    // silu(g)*u
__device__ __nv_bfloat16 g_D[(size_t)PADROWS*DIM];     // down output (bf16)

// ------------------------------- helpers -----------------------------------
__device__ __forceinline__ uint2 cvt4(float4 v) {
    __nv_bfloat162 lo = __floats2bfloat162_rn(v.x, v.y);
    __nv_bfloat162 hi = __floats2bfloat162_rn(v.z, v.w);
    uint2 r;
    r.x = *reinterpret_cast<unsigned*>(&lo);
    r.y = *reinterpret_cast<unsigned*>(&hi);
    return r;
}

__device__ __forceinline__ void mma16816(float* d, const unsigned* a, const unsigned* b) {
    asm volatile(
        "mma.sync.aligned.m16n8k16.row.col.f32.bf16.bf16.f32 "
        "{%0,%1,%2,%3}, {%4,%5,%6,%7}, {%8,%9}, {%0,%1,%2,%3};\n"
        : "+f"(d[0]), "+f"(d[1]), "+f"(d[2]), "+f"(d[3])
        : "r"(a[0]), "r"(a[1]), "r"(a[2]), "r"(a[3]), "r"(b[0]), "r"(b[1]));
}

__device__ __forceinline__ void ldsm4(unsigned &r0, unsigned &r1, unsigned &r2,
                                      unsigned &r3, uint32_t addr) {
    asm volatile("ldmatrix.sync.aligned.m8n8.x4.shared.b16 {%0,%1,%2,%3}, [%4];\n"
                 : "=r"(r0), "=r"(r1), "=r"(r2), "=r"(r3) : "r"(addr));
}

__device__ __forceinline__ void cpa16(uint32_t dst, const void* src) {
    asm volatile("cp.async.cg.shared.global [%0], [%1], 16;\n" :: "r"(dst), "l"(src));
}
__device__ __forceinline__ void cpa16z(uint32_t dst, const void* src, int sz) {
    asm volatile("cp.async.cg.shared.global [%0], [%1], 16, %2;\n"
                 :: "r"(dst), "l"(src), "r"(sz));
}
#define CP_COMMIT asm volatile("cp.async.commit_group;\n")
template<int N> __device__ __forceinline__ void cp_wait() {
    asm volatile("cp.async.wait_group %0;\n" :: "n"(N));
}

// packed fp32x2 helpers
__device__ __forceinline__ void fma2(uint64_t& d, uint64_t a, uint64_t b) {
    asm("fma.rn.f32x2 %0, %1, %2, %3;" : "=l"(d) : "l"(a), "l"(b), "l"(d));
}
__device__ __forceinline__ uint64_t packf2(float lo, float hi) {
    uint64_t r;
    asm("mov.b64 %0, {%1, %2};" : "=l"(r) : "f"(lo), "f"(hi));
    return r;
}
__device__ __forceinline__ void unpackf2(uint64_t p, float& lo, float& hi) {
    asm("mov.b64 {%0, %1}, %2;" : "=f"(lo), "=f"(hi) : "l"(p));
}

// local padded-offset derivation from g_counts
__device__ __forceinline__ int make_offs(int* offs) {
    int o = 0;
#pragma unroll
    for (int e = 0; e < NE; e++) {
        offs[e] = o;
        o += ((g_counts[e] + 127) >> 7) << 7;
    }
    offs[NE] = o;
    return o;
}

// ---- fold + router + xconv fused launch (z: 0-1 router, 2 xconv, 3+ fold) --
__global__ __launch_bounds__(256) void fold_router_kernel(
        const float* __restrict__ X,   const float* __restrict__ Wgate,
        const float* __restrict__ Wg_, const float* __restrict__ Ag_,
        const float* __restrict__ Bg_,
        const float* __restrict__ Wu_, const float* __restrict__ Au_,
        const float* __restrict__ Bu_,
        const float* __restrict__ Wd_, const float* __restrict__ Ad_,
        const float* __restrict__ Bd_,
        __nv_bfloat16* __restrict__ Og_, __nv_bfloat16* __restrict__ Ou_,
        __nv_bfloat16* __restrict__ Od_) {
    int z = blockIdx.z;
    if (z < 2) {
        // ---------------- router path ----------------
        int rblk = z * 512 + blockIdx.y * 16 + blockIdx.x;   // 0..1023
        int warp = threadIdx.x >> 5, lane = threadIdx.x & 31;
        int t = rblk * 8 + warp;
        if (t >= T_TOK) return;
        const float4* xr = (const float4*)(X + (size_t)t * DIM);
        float acc[NE];
#pragma unroll
        for (int e = 0; e < NE; e++) acc[e] = 0.f;
        for (int i = lane; i < DIM/4; i += 32) {
            float4 xv = xr[i];
#pragma unroll
            for (int e = 0; e < NE; e++) {
                float4 w = ((const float4*)(Wgate + (size_t)e * DIM))[i];
                acc[e] += xv.x*w.x + xv.y*w.y + xv.z*w.z + xv.w*w.w;
            }
        }
#pragma unroll
        for (int e = 0; e < NE; e++)
#pragma unroll
            for (int o = 16; o > 0; o >>= 1)
                acc[e] += __shfl_xor_sync(0xffffffffu, acc[e], o);

        if (lane == 0) {
            int e0 = 0;
#pragma unroll
            for (int e = 1; e < NE; e++) if (acc[e] > acc[e0]) e0 = e;
            int e1 = (e0 == 0) ? 1 : 0;
#pragma unroll
            for (int e = 0; e < NE; e++)
                if (e != e0 && acc[e] > acc[e1]) e1 = e;

            float m = acc[e0];
            float s = 0.f;
#pragma unroll
            for (int e = 0; e < NE; e++) s += expf(acc[e] - m);
            float lse = logf(s) + m;
            atomicAdd(&g_zsum, lse * lse);

            float d = expf(acc[e1] - acc[e0]);
            float p0 = 1.f / (1.f + d);
            float p1 = d / (1.f + d);

            int s0 = atomicAdd(&g_counts[e0], 1);
            int s1 = atomicAdd(&g_counts[e1], 1);
            g_tok[e0*T_TOK + s0] = t;
            g_tok[e1*T_TOK + s1] = t;
            atomicAdd(&g_importance[e0], p0);
            atomicAdd(&g_importance[e1], p1);
            g_re[2*t] = e0;  g_rs[2*t] = s0;  g_rg[2*t] = p0;
            g_re[2*t+1] = e1; g_rs[2*t+1] = s1; g_rg[2*t+1] = p1;
        }
        return;
    }
    if (z == 2) {
        // ---------------- dense X fp32 -> bf16 ----------------
        int b = blockIdx.y * 16 + blockIdx.x;   // 0..511
        const float4* src = (const float4*)X;
        uint2* dst = (uint2*)g_Xb;
        int base = b * 8192 + threadIdx.x;      // float4 units
#pragma unroll
        for (int i = 0; i < 32; i++)
            dst[base + i*256] = cvt4(src[base + i*256]);
        return;
    }

    // ---------------- fold path ----------------
    int zz = z - 3;
    int wsel = zz >> 3;          // 0=gate, 1=up, 2=down
    int e = zz & 7;
    const float* W = (wsel == 0) ? Wg_ : (wsel == 1) ? Wu_ : Wd_;
    const float* A = (wsel == 0) ? Ag_ : (wsel == 1) ? Au_ : Ad_;
    const float* B = (wsel == 0) ? Bg_ : (wsel == 1) ? Bu_ : Bd_;
    __nv_bfloat16* out = (wsel == 0) ? Og_ : (wsel == 1) ? Ou_ : Od_;

    int tid = threadIdx.x;
    int n  = blockIdx.y * 64 + (tid >> 2);
    int k0 = blockIdx.x * 128;

    __shared__ float As[NR][128];
#pragma unroll
    for (int i = 0; i < 8; i++) {
        int idx = tid + i * 256;
        As[idx >> 7][idx & 127] = A[((size_t)e*NR + (idx >> 7))*DIM + k0 + (idx & 127)];
    }
    __syncthreads();

    uint64_t Brp[NR];
    {
        const float4* b4 = (const float4*)(B + ((size_t)e*DIM + n)*NR);
#pragma unroll
        for (int q = 0; q < 4; q++) {
            float4 v = b4[q];
            Brp[q*4+0] = packf2(SCALING * v.x, SCALING * v.x);
            Brp[q*4+1] = packf2(SCALING * v.y, SCALING * v.y);
            Brp[q*4+2] = packf2(SCALING * v.z, SCALING * v.z);
            Brp[q*4+3] = packf2(SCALING * v.w, SCALING * v.w);
        }
    }

    const float* Wrow = W + ((size_t)e*DIM + n)*DIM + k0;
    __nv_bfloat16* Orow = out + ((size_t)e*DIM + n)*DIM + k0;
#pragma unroll
    for (int q = 0; q < 8; q++) {
        int k = q*16 + (tid & 3)*4;
        float4 w = *(const float4*)(Wrow + k);
        uint64_t p01 = packf2(w.x, w.y);
        uint64_t p23 = packf2(w.z, w.w);
#pragma unroll
        for (int r = 0; r < NR; r++) {
            uint64_t a01 = *(const uint64_t*)&As[r][k];
            uint64_t a23 = *(const uint64_t*)&As[r][k+2];
            fma2(p01, Brp[r], a01);
            fma2(p23, Brp[r], a23);
        }
        float f0, f1, f2, f3;
        unpackf2(p01, f0, f1);
        unpackf2(p23, f2, f3);
        __nv_bfloat162 lo = __floats2bfloat162_rn(f0, f1);
        __nv_bfloat162 hi = __floats2bfloat162_rn(f2, f3);
        uint2 o;
        o.x = *reinterpret_cast<unsigned*>(&lo);
        o.y = *reinterpret_cast<unsigned*>(&hi);
        *(uint2*)(Orow + k) = o;
    }
}

// ----------------------- fused gate+up GEMM (mma.sync) ----------------------
// A rows gathered on the fly via smem toks[] (zero-fill for pad slots).
__global__ __launch_bounds__(256, 2) void gu_gemm_kernel() {
    int offs[NE+1];
    int total = make_offs(offs);
    int tile = blockIdx.y;
    if (tile * 128 >= total) return;
    int e = 0;
#pragma unroll
    for (int q = 0; q < NE; q++)
        if (tile * 128 >= offs[q]) e = q;
    int cnt = g_counts[e];
    int base_slot = tile * 128 - offs[e];
    int rowbase = tile * 128;
    int n0 = blockIdx.x * 64;
    int tid = threadIdx.x;

    extern __shared__ __nv_bfloat16 smem[];
    uint32_t smBase = (uint32_t)__cvta_generic_to_shared(smem);
    int* toks = (int*)(smem + 3*GU_STG);
    if (tid < 128) {
        int slot = base_slot + tid;
        toks[tid] = (slot < cnt) ? g_tok[e*T_TOK + slot] : -1;
    }
    __syncthreads();

    auto loadStage = [&](int s) {
        uint32_t buf = smBase + (uint32_t)(s % 3) * (GU_STG * 2);
        int k0 = s * BK;
#pragma unroll
        for (int it = 0; it < 4; it++) {           // A: 1024 x 16B, gathered
            int c = tid + it * 256;
            int row = c >> 3, ch = c & 7;
            uint32_t d = buf + (uint32_t)(row*64 + ((ch ^ (row & 7)) * 8)) * 2;
            int tk = toks[row];
            const __nv_bfloat16* src =
                g_Xb + (size_t)(tk < 0 ? 0 : tk)*DIM + k0 + ch*8;
            cpa16z(d, src, (tk < 0) ? 0 : 16);
        }
#pragma unroll
        for (int it = 0; it < 2; it++) {           // Bg: 512 x 16B
            int c = tid + it * 256;
            int row = c >> 3, ch = c & 7;
            uint32_t d = buf + (uint32_t)(8192 + row*64 + ((ch ^ (row & 7)) * 8)) * 2;
            cpa16(d, g_Wgb + ((size_t)e*DIM + n0 + row)*DIM + k0 + ch*8);
        }
#pragma unroll
        for (int it = 0; it < 2; it++) {           // Bu
            int c = tid + it * 256;
            int row = c >> 3, ch = c & 7;
            uint32_t d = buf + (uint32_t)(12288 + row*64 + ((ch ^ (row & 7)) * 8)) * 2;
            cpa16(d, g_Wub + ((size_t)e*DIM + n0 + row)*DIM + k0 + ch*8);
        }
    };

    float ag[2][4][4], au[2][4][4];
#pragma unroll
    for (int mt = 0; mt < 2; mt++)
#pragma unroll
        for (int nt = 0; nt < 4; nt++)
#pragma unroll
            for (int i = 0; i < 4; i++) { ag[mt][nt][i] = 0.f; au[mt][nt][i] = 0.f; }

    int lane = tid & 31, warp = tid >> 5;
    int wm = warp & 3, wn = warp >> 2;    // 4x2 warps; 32 rows x 32 cols each

    loadStage(0); CP_COMMIT;
    loadStage(1); CP_COMMIT;

    for (int s = 0; s < NS; s++) {
        cp_wait<1>();
        __syncthreads();
        if (s + 2 < NS) loadStage(s + 2);
        CP_COMMIT;

        uint32_t buf = smBase + (uint32_t)(s % 3) * (GU_STG * 2);
#pragma unroll
        for (int kk = 0; kk < BK; kk += 16) {
            int kh = kk + ((lane >> 4) << 3);
            unsigned af[2][4];
#pragma unroll
            for (int mt = 0; mt < 2; mt++) {
                int arow = wm*32 + mt*16 + (lane & 15);
                uint32_t a = buf + (uint32_t)(arow*64 +
                              (((kh >> 3) ^ (arow & 7)) << 3)) * 2;
                ldsm4(af[mt][0], af[mt][1], af[mt][2], af[mt][3], a);
            }
            unsigned bg[4][2];
#pragma unroll
            for (int p = 0; p < 2; p++) {
                int brow = wn*32 + p*16 + (lane & 15);
                uint32_t b = buf + (uint32_t)(8192 + brow*64 +
                              (((kh >> 3) ^ (brow & 7)) << 3)) * 2;
                unsigned q0, q1, q2, q3;
                ldsm4(q0, q1, q2, q3, b);
                bg[2*p][0] = q0; bg[2*p][1] = q2;
                bg[2*p+1][0] = q1; bg[2*p+1][1] = q3;
            }
#pragma unroll
            for (int mt = 0; mt < 2; mt++)
#pragma unroll
                for (int nt = 0; nt < 4; nt++)
                    mma16816(ag[mt][nt], af[mt], bg[nt]);
            unsigned bu[4][2];
#pragma unroll
            for (int p = 0; p < 2; p++) {
                int brow = wn*32 + p*16 + (lane & 15);
                uint32_t b = buf + (uint32_t)(12288 + brow*64 +
                              (((kh >> 3) ^ (brow & 7)) << 3)) * 2;
                unsigned q0, q1, q2, q3;
                ldsm4(q0, q1, q2, q3, b);
                bu[2*p][0] = q0; bu[2*p][1] = q2;
                bu[2*p+1][0] = q1; bu[2*p+1][1] = q3;
            }
#pragma unroll
            for (int mt = 0; mt < 2; mt++)
#pragma unroll
                for (int nt = 0; nt < 4; nt++)
                    mma16816(au[mt][nt], af[mt], bu[nt]);
        }
    }

    // epilogue: a = silu(g) * u -> g_A2 bf16 (pad rows produce zeros)
    int g = lane >> 2, t4 = lane & 3;
#pragma unroll
    for (int mt = 0; mt < 2; mt++) {
#pragma unroll
        for (int hrow = 0; hrow < 2; hrow++) {
            int r = wm*32 + mt*16 + g + hrow*8;
            __nv_bfloat16* dst = g_A2 + (size_t)(rowbase + r)*DIM + n0;
#pragma unroll
            for (int nt = 0; nt < 4; nt++) {
                int c = wn*32 + nt*8 + 2*t4;
                float g0 = ag[mt][nt][hrow*2 + 0];
                float g1 = ag[mt][nt][hrow*2 + 1];
                float u0 = au[mt][nt][hrow*2 + 0];
                float u1 = au[mt][nt][hrow*2 + 1];
                float a0 = g0 / (1.f + __expf(-g0)) * u0;
                float a1 = g1 / (1.f + __expf(-g1)) * u1;
                __nv_bfloat162 p = __floats2bfloat162_rn(a0, a1);
                *(unsigned*)(dst + c) = *reinterpret_cast<unsigned*>(&p);
            }
        }
    }
}

// ----------------------------- down GEMM ------------------------------------
__global__ __launch_bounds__(256, 2) void d_gemm_kernel() {
    int offs[NE+1];
    int total = make_offs(offs);
    int tile = blockIdx.y;
    int tid = threadIdx.x;
    if (blockIdx.x == 0 && tile == 0 && tid <= NE)
        g_offsets[tid] = offs[tid];          // publish for combine
    if (tile * 128 >= total) return;
    int e = 0;
#pragma unroll
    for (int q = 0; q < NE; q++)
        if (tile * 128 >= offs[q]) e = q;
    int rowbase = tile * 128;
    int n0 = blockIdx.x * 128;

    extern __shared__ __nv_bfloat16 smem[];
    uint32_t smBase = (uint32_t)__cvta_generic_to_shared(smem);

    auto loadStage = [&](int s) {
        uint32_t buf = smBase + (uint32_t)(s % 3) * (D_STG * 2);
        int k0 = s * BK;
#pragma unroll
        for (int it = 0; it < 4; it++) {               // A
            int c = tid + it * 256;
            int row = c >> 3, ch = c & 7;
            uint32_t d = buf + (uint32_t)(row*64 + ((ch ^ (row & 7)) * 8)) * 2;
            cpa16(d, g_A2 + (size_t)(rowbase + row)*DIM + k0 + ch*8);
        }
#pragma unroll
        for (int it = 0; it < 4; it++) {               // B
            int c = tid + it * 256;
            int row = c >> 3, ch = c & 7;
            uint32_t d = buf + (uint32_t)(8192 + row*64 + ((ch ^ (row & 7)) * 8)) * 2;
            cpa16(d, g_Wdb + ((size_t)e*DIM + n0 + row)*DIM + k0 + ch*8);
        }
    };

    float acc[2][8][4];
#pragma unroll
    for (int mt = 0; mt < 2; mt++)
#pragma unroll
        for (int nt = 0; nt < 8; nt++)
#pragma unroll
            for (int i = 0; i < 4; i++) acc[mt][nt][i] = 0.f;

    int lane = tid & 31, warp = tid >> 5;
    int wm = warp & 3, wn = warp >> 2;    // warp tile 32 x 64

    loadStage(0); CP_COMMIT;
    loadStage(1); CP_COMMIT;

    for (int s = 0; s < NS; s++) {
        cp_wait<1>();
        __syncthreads();
        if (s + 2 < NS) loadStage(s + 2);
        CP_COMMIT;

        uint32_t buf = smBase + (uint32_t)(s % 3) * (D_STG * 2);
#pragma unroll
        for (int kk = 0; kk < BK; kk += 16) {
            int kh = kk + ((lane >> 4) << 3);
            unsigned af[2][4];
#pragma unroll
            for (int mt = 0; mt < 2; mt++) {
                int arow = wm*32 + mt*16 + (lane & 15);
                uint32_t a = buf + (uint32_t)(arow*64 +
                              (((kh >> 3) ^ (arow & 7)) << 3)) * 2;
                ldsm4(af[mt][0], af[mt][1], af[mt][2], af[mt][3], a);
            }
            unsigned bq[8][2];
#pragma unroll
            for (int p = 0; p < 4; p++) {
                int brow = wn*64 + p*16 + (lane & 15);
                uint32_t b = buf + (uint32_t)(8192 + brow*64 +
                              (((kh >> 3) ^ (brow & 7)) << 3)) * 2;
                unsigned q0, q1, q2, q3;
                ldsm4(q0, q1, q2, q3, b);
                bq[2*p][0]   = q0; bq[2*p][1]   = q2;
                bq[2*p+1][0] = q1; bq[2*p+1][1] = q3;
            }
#pragma unroll
            for (int mt = 0; mt < 2; mt++)
#pragma unroll
                for (int nt = 0; nt < 8; nt++)
                    mma16816(acc[mt][nt], af[mt], bq[nt]);
        }
    }

    int g = lane >> 2, t4 = lane & 3;
#pragma unroll
    for (int mt = 0; mt < 2; mt++) {
#pragma unroll
        for (int hrow = 0; hrow < 2; hrow++) {
            int r = wm*32 + mt*16 + g + hrow*8;
            __nv_bfloat16* dst = g_D + (size_t)(rowbase + r)*DIM + n0;
#pragma unroll
            for (int nt = 0; nt < 8; nt++) {
                int c = wn*64 + nt*8 + 2*t4;
                __nv_bfloat162 p = __floats2bfloat162_rn(
                    acc[mt][nt][hrow*2], acc[mt][nt][hrow*2 + 1]);
                *(unsigned*)(dst + c) = *reinterpret_cast<unsigned*>(&p);
            }
        }
    }
}

// ----------------- combine (+loss, +re-init for next replay) ----------------
__global__ void combine_kernel(const float* __restrict__ Xh,
                               const float* __restrict__ alpha,
                               float* __restrict__ out, int lossidx) {
    int t = blockIdx.x;
    if (t == 0 && threadIdx.x == 0) {
        float s = 0.f;
        for (int e = 0; e < NE; e++) s += g_importance[e] * (float)g_counts[e];
        float lb = AUXC * ((float)NE * s / ((float)T_TOK * (float)T_TOK));
        float z  = ZC * (g_zsum / (float)T_TOK);
        out[lossidx] = lb + z;
        // re-zero routing state for the next replay (this thread is the only
        // remaining reader of counts/importance/zsum).
        for (int e = 0; e < NE; e++) { g_counts[e] = 0; g_importance[e] = 0.f; }
        g_zsum = 0.f;
    }
    int e0 = g_re[2*t], e1 = g_re[2*t+1];
    size_t r0 = (size_t)(g_offsets[e0] + g_rs[2*t]) * DIM;
    size_t r1 = (size_t)(g_offsets[e1] + g_rs[2*t+1]) * DIM;
    float al = alpha[0];
    float w0 = g_rg[2*t] * al, w1 = g_rg[2*t+1] * al;
    const float4* h4 = (const float4*)(Xh + (size_t)t * DIM);
    const __nv_bfloat16* d0 = g_D + r0;
    const __nv_bfloat16* d1 = g_D + r1;
    float4* o4 = (float4*)(out + (size_t)t * DIM);
    for (int i = threadIdx.x; i < DIM/4; i += blockDim.x) {
        float4 h = h4[i];
        uint2 a2 = *(const uint2*)(d0 + i*4);
        uint2 b2 = *(const uint2*)(d1 + i*4);
        float2 a0 = __bfloat1622float2(*reinterpret_cast<__nv_bfloat162*>(&a2.x));
        float2 a1 = __bfloat1622float2(*reinterpret_cast<__nv_bfloat162*>(&a2.y));
        float2 b0 = __bfloat1622float2(*reinterpret_cast<__nv_bfloat162*>(&b2.x));
        float2 b1 = __bfloat1622float2(*reinterpret_cast<__nv_bfloat162*>(&b2.y));
        float4 r;
        r.x = h.x + w0*a0.x + w1*b0.x;
        r.y = h.y + w0*a0.y + w1*b0.y;
        r.z = h.z + w0*a1.x + w1*b1.x;
        r.w = h.w + w0*a1.y + w1*b1.y;
        o4[i] = r;
    }
}

// ------------------------------- launcher -----------------------------------
extern "C" void kernel_launch(void* const* d_in, const int* in_sizes, int n_in,
                              void* d_out, int out_size) {
    const float* X      = (const float*)d_in[0];
    const float* Wg     = (const float*)d_in[1];
    const float* gate_w = (const float*)d_in[2];
    const float* gate_A = (const float*)d_in[3];
    const float* gate_B = (const float*)d_in[4];
    const float* up_w   = (const float*)d_in[5];
    const float* up_A   = (const float*)d_in[6];
    const float* up_B   = (const float*)d_in[7];
    const float* down_w = (const float*)d_in[8];
    const float* down_A = (const float*)d_in[9];
    const float* down_B = (const float*)d_in[10];
    const float* alpha  = (const float*)d_in[11];
    float* out = (float*)d_out;

    cudaFuncSetAttribute(gu_gemm_kernel, cudaFuncAttributeMaxDynamicSharedMemorySize, GU_SMEM);
    cudaFuncSetAttribute(d_gemm_kernel,  cudaFuncAttributeMaxDynamicSharedMemorySize, D_SMEM);

    __nv_bfloat16 *dWgb, *dWub, *dWdb;
    cudaGetSymbolAddress((void**)&dWgb, g_Wgb);
    cudaGetSymbolAddress((void**)&dWub, g_Wub);
    cudaGetSymbolAddress((void**)&dWdb, g_Wdb);

    // 0: fold + router + dense X conversion
    dim3 frgrid(DIM/128, DIM/64, 3*NE + 3);
    fold_router_kernel<<<frgrid, 256>>>(X, Wg,
                                        gate_w, gate_A, gate_B,
                                        up_w,   up_A,   up_B,
                                        down_w, down_A, down_B,
                                        dWgb, dWub, dWdb);

    // 1: fused gate+up GEMM (gathers A rows via toks[]) -> g_A2
    dim3 gugrid(DIM/64, MAXTILES);
    gu_gemm_kernel<<<gugrid, 256, GU_SMEM>>>();

    // 2: down GEMM -> g_D (publishes g_offsets)
    dim3 dgrid(DIM/128, MAXTILES);
    d_gemm_kernel<<<dgrid, 256, D_SMEM>>>();

    // 3: combine (+loss, +re-init)
    combine_kernel<<<T_TOK, 256>>>(X, alpha, out, out_size - 1);
}

// round 15
// speedup vs baseline: 1.0449x; 1.0262x over previous
#include <cuda_runtime.h>
#include <cuda_bf16.h>
#include <math.h>
#include <stdint.h>

// ---------------------------------------------------------------------------
// MoE + LoRA forward, routed top-2/8. Legacy mma.sync bf16 tensor path.
// Round 15: gu and down GEMMs fused into ONE launch with per-tile ready
// counters (gu blocks first in grid; d blocks spin on tilecnt[tile]==32).
// Overlaps gu tail waves with d head. Bodies identical to 1385us baseline.
// 3 launches: fold(+router+xconv), fused_gemm, combine(+loss+reset).
// ---------------------------------------------------------------------------

#define DIM    2048
#define T_TOK  8192
#define NE     8
#define NR     16
#define NROWS  (T_TOK*2)
#define PADROWS (NROWS + NE*128)      // per-expert counts padded to 128
#define MAXTILES (PADROWS/128)        // 136
#define SCALING 2.0f
#define AUXC   0.01f
#define ZC     0.001f

#define BK 64
#define NS 32                              // 2048 / 64 K-stages
#define GU_STG (128*64 + 64*64 + 64*64)    // halves/stage: A + Bg + Bu
#define D_STG  (128*64 + 128*64)           // halves/stage: A + B
#define FUSED_SMEM (3*GU_STG*2 + 512)      // max(gu, d) + toks
#define NGU (32*MAXTILES)                  // 4352 gu blocks
#define ND  (16*MAXTILES)                  // 2176 d blocks

// ------------------------- scratch (device globals) ------------------------
// Zero-initialized at module load; combine re-zeroes routing state + tile
// counters each call, so every graph replay starts clean.
__device__ int   g_counts[NE];
__device__ int   g_offsets[NE+1];     // published by fused kernel for combine
__device__ float g_importance[NE];
__device__ float g_zsum;
__device__ int   g_tilecnt[MAXTILES]; // gu-CTAs-finished count per row tile
__device__ int   g_tok[NE*T_TOK];
__device__ int   g_re[NROWS];
__device__ int   g_rs[NROWS];
__device__ float g_rg[NROWS];

__device__ __nv_bfloat16 g_Xb[(size_t)T_TOK*DIM];      // dense bf16 X
__device__ __nv_bfloat16 g_Wgb[(size_t)NE*DIM*DIM];    // folded bf16 weights
__device__ __nv_bfloat16 g_Wub[(size_t)NE*DIM*DIM];
__device__ __nv_bfloat16 g_Wdb[(size_t)NE*DIM*DIM];

__device__ __nv_bfloat16 g_A2[(size_t)PADROWS*DIM];    // silu(g)*u
__device__ __nv_bfloat16 g_D[(size_t)PADROWS*DIM];     // down output (bf16)

// ------------------------------- helpers -----------------------------------
__device__ __forceinline__ uint2 cvt4(float4 v) {
    __nv_bfloat162 lo = __floats2bfloat162_rn(v.x, v.y);
    __nv_bfloat162 hi = __floats2bfloat162_rn(v.z, v.w);
    uint2 r;
    r.x = *reinterpret_cast<unsigned*>(&lo);
    r.y = *reinterpret_cast<unsigned*>(&hi);
    return r;
}

__device__ __forceinline__ void mma16816(float* d, const unsigned* a, const unsigned* b) {
    asm volatile(
        "mma.sync.aligned.m16n8k16.row.col.f32.bf16.bf16.f32 "
        "{%0,%1,%2,%3}, {%4,%5,%6,%7}, {%8,%9}, {%0,%1,%2,%3};\n"
        : "+f"(d[0]), "+f"(d[1]), "+f"(d[2]), "+f"(d[3])
        : "r"(a[0]), "r"(a[1]), "r"(a[2]), "r"(a[3]), "r"(b[0]), "r"(b[1]));
}

__device__ __forceinline__ void ldsm4(unsigned &r0, unsigned &r1, unsigned &r2,
                                      unsigned &r3, uint32_t addr) {
    asm volatile("ldmatrix.sync.aligned.m8n8.x4.shared.b16 {%0,%1,%2,%3}, [%4];\n"
                 : "=r"(r0), "=r"(r1), "=r"(r2), "=r"(r3) : "r"(addr));
}

__device__ __forceinline__ void cpa16(uint32_t dst, const void* src) {
    asm volatile("cp.async.cg.shared.global [%0], [%1], 16;\n" :: "r"(dst), "l"(src));
}
__device__ __forceinline__ void cpa16z(uint32_t dst, const void* src, int sz) {
    asm volatile("cp.async.cg.shared.global [%0], [%1], 16, %2;\n"
                 :: "r"(dst), "l"(src), "r"(sz));
}
#define CP_COMMIT asm volatile("cp.async.commit_group;\n")
template<int N> __device__ __forceinline__ void cp_wait() {
    asm volatile("cp.async.wait_group %0;\n" :: "n"(N));
}

// packed fp32x2 helpers
__device__ __forceinline__ void fma2(uint64_t& d, uint64_t a, uint64_t b) {
    asm("fma.rn.f32x2 %0, %1, %2, %3;" : "=l"(d) : "l"(a), "l"(b), "l"(d));
}
__device__ __forceinline__ uint64_t packf2(float lo, float hi) {
    uint64_t r;
    asm("mov.b64 %0, {%1, %2};" : "=l"(r) : "f"(lo), "f"(hi));
    return r;
}
__device__ __forceinline__ void unpackf2(uint64_t p, float& lo, float& hi) {
    asm("mov.b64 {%0, %1}, %2;" : "=f"(lo), "=f"(hi) : "l"(p));
}

// local padded-offset derivation from g_counts
__device__ __forceinline__ int make_offs(int* offs) {
    int o = 0;
#pragma unroll
    for (int e = 0; e < NE; e++) {
        offs[e] = o;
        o += ((g_counts[e] + 127) >> 7) << 7;
    }
    offs[NE] = o;
    return o;
}

// ---- fold + router + xconv fused launch (z: 0-1 router, 2 xconv, 3+ fold) --
__global__ __launch_bounds__(256) void fold_router_kernel(
        const float* __restrict__ X,   const float* __restrict__ Wgate,
        const float* __restrict__ Wg_, const float* __restrict__ Ag_,
        const float* __restrict__ Bg_,
        const float* __restrict__ Wu_, const float* __restrict__ Au_,
        const float* __restrict__ Bu_,
        const float* __restrict__ Wd_, const float* __restrict__ Ad_,
        const float* __restrict__ Bd_,
        __nv_bfloat16* __restrict__ Og_, __nv_bfloat16* __restrict__ Ou_,
        __nv_bfloat16* __restrict__ Od_) {
    int z = blockIdx.z;
    if (z < 2) {
        // ---------------- router path ----------------
        int rblk = z * 512 + blockIdx.y * 16 + blockIdx.x;   // 0..1023
        int warp = threadIdx.x >> 5, lane = threadIdx.x & 31;
        int t = rblk * 8 + warp;
        if (t >= T_TOK) return;
        const float4* xr = (const float4*)(X + (size_t)t * DIM);
        float acc[NE];
#pragma unroll
        for (int e = 0; e < NE; e++) acc[e] = 0.f;
        for (int i = lane; i < DIM/4; i += 32) {
            float4 xv = xr[i];
#pragma unroll
            for (int e = 0; e < NE; e++) {
                float4 w = ((const float4*)(Wgate + (size_t)e * DIM))[i];
                acc[e] += xv.x*w.x + xv.y*w.y + xv.z*w.z + xv.w*w.w;
            }
        }
#pragma unroll
        for (int e = 0; e < NE; e++)
#pragma unroll
            for (int o = 16; o > 0; o >>= 1)
                acc[e] += __shfl_xor_sync(0xffffffffu, acc[e], o);

        if (lane == 0) {
            int e0 = 0;
#pragma unroll
            for (int e = 1; e < NE; e++) if (acc[e] > acc[e0]) e0 = e;
            int e1 = (e0 == 0) ? 1 : 0;
#pragma unroll
            for (int e = 0; e < NE; e++)
                if (e != e0 && acc[e] > acc[e1]) e1 = e;

            float m = acc[e0];
            float s = 0.f;
#pragma unroll
            for (int e = 0; e < NE; e++) s += expf(acc[e] - m);
            float lse = logf(s) + m;
            atomicAdd(&g_zsum, lse * lse);

            float d = expf(acc[e1] - acc[e0]);
            float p0 = 1.f / (1.f + d);
            float p1 = d / (1.f + d);

            int s0 = atomicAdd(&g_counts[e0], 1);
            int s1 = atomicAdd(&g_counts[e1], 1);
            g_tok[e0*T_TOK + s0] = t;
            g_tok[e1*T_TOK + s1] = t;
            atomicAdd(&g_importance[e0], p0);
            atomicAdd(&g_importance[e1], p1);
            g_re[2*t] = e0;  g_rs[2*t] = s0;  g_rg[2*t] = p0;
            g_re[2*t+1] = e1; g_rs[2*t+1] = s1; g_rg[2*t+1] = p1;
        }
        return;
    }
    if (z == 2) {
        // ---------------- dense X fp32 -> bf16 ----------------
        int b = blockIdx.y * 16 + blockIdx.x;   // 0..511
        const float4* src = (const float4*)X;
        uint2* dst = (uint2*)g_Xb;
        int base = b * 8192 + threadIdx.x;      // float4 units
#pragma unroll
        for (int i = 0; i < 32; i++)
            dst[base + i*256] = cvt4(src[base + i*256]);
        return;
    }

    // ---------------- fold path ----------------
    int zz = z - 3;
    int wsel = zz >> 3;          // 0=gate, 1=up, 2=down
    int e = zz & 7;
    const float* W = (wsel == 0) ? Wg_ : (wsel == 1) ? Wu_ : Wd_;
    const float* A = (wsel == 0) ? Ag_ : (wsel == 1) ? Au_ : Ad_;
    const float* B = (wsel == 0) ? Bg_ : (wsel == 1) ? Bu_ : Bd_;
    __nv_bfloat16* out = (wsel == 0) ? Og_ : (wsel == 1) ? Ou_ : Od_;

    int tid = threadIdx.x;
    int n  = blockIdx.y * 64 + (tid >> 2);
    int k0 = blockIdx.x * 128;

    __shared__ float As[NR][128];
#pragma unroll
    for (int i = 0; i < 8; i++) {
        int idx = tid + i * 256;
        As[idx >> 7][idx & 127] = A[((size_t)e*NR + (idx >> 7))*DIM + k0 + (idx & 127)];
    }
    __syncthreads();

    uint64_t Brp[NR];
    {
        const float4* b4 = (const float4*)(B + ((size_t)e*DIM + n)*NR);
#pragma unroll
        for (int q = 0; q < 4; q++) {
            float4 v = b4[q];
            Brp[q*4+0] = packf2(SCALING * v.x, SCALING * v.x);
            Brp[q*4+1] = packf2(SCALING * v.y, SCALING * v.y);
            Brp[q*4+2] = packf2(SCALING * v.z, SCALING * v.z);
            Brp[q*4+3] = packf2(SCALING * v.w, SCALING * v.w);
        }
    }

    const float* Wrow = W + ((size_t)e*DIM + n)*DIM + k0;
    __nv_bfloat16* Orow = out + ((size_t)e*DIM + n)*DIM + k0;
#pragma unroll
    for (int q = 0; q < 8; q++) {
        int k = q*16 + (tid & 3)*4;
        float4 w = *(const float4*)(Wrow + k);
        uint64_t p01 = packf2(w.x, w.y);
        uint64_t p23 = packf2(w.z, w.w);
#pragma unroll
        for (int r = 0; r < NR; r++) {
            uint64_t a01 = *(const uint64_t*)&As[r][k];
            uint64_t a23 = *(const uint64_t*)&As[r][k+2];
            fma2(p01, Brp[r], a01);
            fma2(p23, Brp[r], a23);
        }
        float f0, f1, f2, f3;
        unpackf2(p01, f0, f1);
        unpackf2(p23, f2, f3);
        __nv_bfloat162 lo = __floats2bfloat162_rn(f0, f1);
        __nv_bfloat162 hi = __floats2bfloat162_rn(f2, f3);
        uint2 o;
        o.x = *reinterpret_cast<unsigned*>(&lo);
        o.y = *reinterpret_cast<unsigned*>(&hi);
        *(uint2*)(Orow + k) = o;
    }
}

// ------------------- fused gu + down GEMM (one launch) -----------------------
// Blocks [0, NGU): gate+up GEMM (signals g_tilecnt[tile] on completion).
// Blocks [NGU, NGU+ND): down GEMM (waits for tilecnt[tile]==32 first).
// gu blocks precede d blocks in the grid => dispatch order guarantees progress.
__global__ __launch_bounds__(256, 2) void fused_gemm_kernel() {
    int offs[NE+1];
    int total = make_offs(offs);
    int tid = threadIdx.x;

    extern __shared__ __nv_bfloat16 smem[];
    uint32_t smBase = (uint32_t)__cvta_generic_to_shared(smem);

    if (blockIdx.x < NGU) {
        // =========================== gu path ===========================
        int tile = blockIdx.x >> 5;            // blocks tile-major: tile*32+n
        if (tile * 128 >= total) return;
        int n0 = (blockIdx.x & 31) * 64;
        int e = 0;
#pragma unroll
        for (int q = 0; q < NE; q++)
            if (tile * 128 >= offs[q]) e = q;
        int cnt = g_counts[e];
        int base_slot = tile * 128 - offs[e];
        int rowbase = tile * 128;

        int* toks = (int*)(smem + 3*GU_STG);
        if (tid < 128) {
            int slot = base_slot + tid;
            toks[tid] = (slot < cnt) ? g_tok[e*T_TOK + slot] : -1;
        }
        __syncthreads();

        auto loadStage = [&](int s) {
            uint32_t buf = smBase + (uint32_t)(s % 3) * (GU_STG * 2);
            int k0 = s * BK;
#pragma unroll
            for (int it = 0; it < 4; it++) {           // A: gathered
                int c = tid + it * 256;
                int row = c >> 3, ch = c & 7;
                uint32_t d = buf + (uint32_t)(row*64 + ((ch ^ (row & 7)) * 8)) * 2;
                int tk = toks[row];
                const __nv_bfloat16* src =
                    g_Xb + (size_t)(tk < 0 ? 0 : tk)*DIM + k0 + ch*8;
                cpa16z(d, src, (tk < 0) ? 0 : 16);
            }
#pragma unroll
            for (int it = 0; it < 2; it++) {           // Bg
                int c = tid + it * 256;
                int row = c >> 3, ch = c & 7;
                uint32_t d = buf + (uint32_t)(8192 + row*64 + ((ch ^ (row & 7)) * 8)) * 2;
                cpa16(d, g_Wgb + ((size_t)e*DIM + n0 + row)*DIM + k0 + ch*8);
            }
#pragma unroll
            for (int it = 0; it < 2; it++) {           // Bu
                int c = tid + it * 256;
                int row = c >> 3, ch = c & 7;
                uint32_t d = buf + (uint32_t)(12288 + row*64 + ((ch ^ (row & 7)) * 8)) * 2;
                cpa16(d, g_Wub + ((size_t)e*DIM + n0 + row)*DIM + k0 + ch*8);
            }
        };

        float ag[2][4][4], au[2][4][4];
#pragma unroll
        for (int mt = 0; mt < 2; mt++)
#pragma unroll
            for (int nt = 0; nt < 4; nt++)
#pragma unroll
                for (int i = 0; i < 4; i++) { ag[mt][nt][i] = 0.f; au[mt][nt][i] = 0.f; }

        int lane = tid & 31, warp = tid >> 5;
        int wm = warp & 3, wn = warp >> 2;

        loadStage(0); CP_COMMIT;
        loadStage(1); CP_COMMIT;

        for (int s = 0; s < NS; s++) {
            cp_wait<1>();
            __syncthreads();
            if (s + 2 < NS) loadStage(s + 2);
            CP_COMMIT;

            uint32_t buf = smBase + (uint32_t)(s % 3) * (GU_STG * 2);
#pragma unroll
            for (int kk = 0; kk < BK; kk += 16) {
                int kh = kk + ((lane >> 4) << 3);
                unsigned af[2][4];
#pragma unroll
                for (int mt = 0; mt < 2; mt++) {
                    int arow = wm*32 + mt*16 + (lane & 15);
                    uint32_t a = buf + (uint32_t)(arow*64 +
                                  (((kh >> 3) ^ (arow & 7)) << 3)) * 2;
                    ldsm4(af[mt][0], af[mt][1], af[mt][2], af[mt][3], a);
                }
                unsigned bg[4][2];
#pragma unroll
                for (int p = 0; p < 2; p++) {
                    int brow = wn*32 + p*16 + (lane & 15);
                    uint32_t b = buf + (uint32_t)(8192 + brow*64 +
                                  (((kh >> 3) ^ (brow & 7)) << 3)) * 2;
                    unsigned q0, q1, q2, q3;
                    ldsm4(q0, q1, q2, q3, b);
                    bg[2*p][0] = q0; bg[2*p][1] = q2;
                    bg[2*p+1][0] = q1; bg[2*p+1][1] = q3;
                }
#pragma unroll
                for (int mt = 0; mt < 2; mt++)
#pragma unroll
                    for (int nt = 0; nt < 4; nt++)
                        mma16816(ag[mt][nt], af[mt], bg[nt]);
                unsigned bu[4][2];
#pragma unroll
                for (int p = 0; p < 2; p++) {
                    int brow = wn*32 + p*16 + (lane & 15);
                    uint32_t b = buf + (uint32_t)(12288 + brow*64 +
                                  (((kh >> 3) ^ (brow & 7)) << 3)) * 2;
                    unsigned q0, q1, q2, q3;
                    ldsm4(q0, q1, q2, q3, b);
                    bu[2*p][0] = q0; bu[2*p][1] = q2;
                    bu[2*p+1][0] = q1; bu[2*p+1][1] = q3;
                }
#pragma unroll
                for (int mt = 0; mt < 2; mt++)
#pragma unroll
                    for (int nt = 0; nt < 4; nt++)
                        mma16816(au[mt][nt], af[mt], bu[nt]);
            }
        }

        // epilogue: a = silu(g) * u -> g_A2 bf16
        int g = lane >> 2, t4 = lane & 3;
#pragma unroll
        for (int mt = 0; mt < 2; mt++) {
#pragma unroll
            for (int hrow = 0; hrow < 2; hrow++) {
                int r = wm*32 + mt*16 + g + hrow*8;
                __nv_bfloat16* dst = g_A2 + (size_t)(rowbase + r)*DIM + n0;
#pragma unroll
                for (int nt = 0; nt < 4; nt++) {
                    int c = wn*32 + nt*8 + 2*t4;
                    float g0 = ag[mt][nt][hrow*2 + 0];
                    float g1 = ag[mt][nt][hrow*2 + 1];
                    float u0 = au[mt][nt][hrow*2 + 0];
                    float u1 = au[mt][nt][hrow*2 + 1];
                    float a0 = g0 / (1.f + __expf(-g0)) * u0;
                    float a1 = g1 / (1.f + __expf(-g1)) * u1;
                    __nv_bfloat162 p = __floats2bfloat162_rn(a0, a1);
                    *(unsigned*)(dst + c) = *reinterpret_cast<unsigned*>(&p);
                }
            }
        }
        // signal: this tile's n-block is done (release)
        __syncthreads();
        __threadfence();
        if (tid == 0) atomicAdd(&g_tilecnt[tile], 1);
        return;
    }

    // ============================ d path ============================
    int b = blockIdx.x - NGU;
    int tile = b >> 4;                         // blocks tile-major: tile*16+n
    if (blockIdx.x == NGU && tid <= NE)
        g_offsets[tid] = offs[tid];            // publish for combine
    if (tile * 128 >= total) return;
    int n0 = (b & 15) * 128;
    int e = 0;
#pragma unroll
    for (int q = 0; q < NE; q++)
        if (tile * 128 >= offs[q]) e = q;
    int rowbase = tile * 128;

    // wait until all 32 gu blocks of this tile have finished (acquire)
    if (tid == 0) {
        volatile int* cnt = &g_tilecnt[tile];
        while (*cnt < 32) __nanosleep(200);
    }
    __syncthreads();
    __threadfence();

    auto loadStage = [&](int s) {
        uint32_t buf = smBase + (uint32_t)(s % 3) * (D_STG * 2);
        int k0 = s * BK;
#pragma unroll
        for (int it = 0; it < 4; it++) {               // A
            int c = tid + it * 256;
            int row = c >> 3, ch = c & 7;
            uint32_t d = buf + (uint32_t)(row*64 + ((ch ^ (row & 7)) * 8)) * 2;
            cpa16(d, g_A2 + (size_t)(rowbase + row)*DIM + k0 + ch*8);
        }
#pragma unroll
        for (int it = 0; it < 4; it++) {               // B
            int c = tid + it * 256;
            int row = c >> 3, ch = c & 7;
            uint32_t d = buf + (uint32_t)(8192 + row*64 + ((ch ^ (row & 7)) * 8)) * 2;
            cpa16(d, g_Wdb + ((size_t)e*DIM + n0 + row)*DIM + k0 + ch*8);
        }
    };

    float acc[2][8][4];
#pragma unroll
    for (int mt = 0; mt < 2; mt++)
#pragma unroll
        for (int nt = 0; nt < 8; nt++)
#pragma unroll
            for (int i = 0; i < 4; i++) acc[mt][nt][i] = 0.f;

    int lane = tid & 31, warp = tid >> 5;
    int wm = warp & 3, wn = warp >> 2;

    loadStage(0); CP_COMMIT;
    loadStage(1); CP_COMMIT;

    for (int s = 0; s < NS; s++) {
        cp_wait<1>();
        __syncthreads();
        if (s + 2 < NS) loadStage(s + 2);
        CP_COMMIT;

        uint32_t buf = smBase + (uint32_t)(s % 3) * (D_STG * 2);
#pragma unroll
        for (int kk = 0; kk < BK; kk += 16) {
            int kh = kk + ((lane >> 4) << 3);
            unsigned af[2][4];
#pragma unroll
            for (int mt = 0; mt < 2; mt++) {
                int arow = wm*32 + mt*16 + (lane & 15);
                uint32_t a = buf + (uint32_t)(arow*64 +
                              (((kh >> 3) ^ (arow & 7)) << 3)) * 2;
                ldsm4(af[mt][0], af[mt][1], af[mt][2], af[mt][3], a);
            }
            unsigned bq[8][2];
#pragma unroll
            for (int p = 0; p < 4; p++) {
                int brow = wn*64 + p*16 + (lane & 15);
                uint32_t b = buf + (uint32_t)(8192 + brow*64 +
                              (((kh >> 3) ^ (brow & 7)) << 3)) * 2;
                unsigned q0, q1, q2, q3;
                ldsm4(q0, q1, q2, q3, b);
                bq[2*p][0]   = q0; bq[2*p][1]   = q2;
                bq[2*p+1][0] = q1; bq[2*p+1][1] = q3;
            }
#pragma unroll
            for (int mt = 0; mt < 2; mt++)
#pragma unroll
                for (int nt = 0; nt < 8; nt++)
                    mma16816(acc[mt][nt], af[mt], bq[nt]);
        }
    }

    int g = lane >> 2, t4 = lane & 3;
#pragma unroll
    for (int mt = 0; mt < 2; mt++) {
#pragma unroll
        for (int hrow = 0; hrow < 2; hrow++) {
            int r = wm*32 + mt*16 + g + hrow*8;
            __nv_bfloat16* dst = g_D + (size_t)(rowbase + r)*DIM + n0;
#pragma unroll
            for (int nt = 0; nt < 8; nt++) {
                int c = wn*64 + nt*8 + 2*t4;
                __nv_bfloat162 p = __floats2bfloat162_rn(
                    acc[mt][nt][hrow*2], acc[mt][nt][hrow*2 + 1]);
                *(unsigned*)(dst + c) = *reinterpret_cast<unsigned*>(&p);
            }
        }
    }
}

// --------- combine (+loss, +re-init of routing state & tile counters) -------
__global__ void combine_kernel(const float* __restrict__ Xh,
                               const float* __restrict__ alpha,
                               float* __restrict__ out, int lossidx) {
    int t = blockIdx.x;
    if (t == 0 && threadIdx.x == 0) {
        float s = 0.f;
        for (int e = 0; e < NE; e++) s += g_importance[e] * (float)g_counts[e];
        float lb = AUXC * ((float)NE * s / ((float)T_TOK * (float)T_TOK));
        float z  = ZC * (g_zsum / (float)T_TOK);
        out[lossidx] = lb + z;
        for (int e = 0; e < NE; e++) { g_counts[e] = 0; g_importance[e] = 0.f; }
        g_zsum = 0.f;
    }
    if (t < MAXTILES && threadIdx.x == 0) g_tilecnt[t] = 0;   // reset for replay
    int e0 = g_re[2*t], e1 = g_re[2*t+1];
    size_t r0 = (size_t)(g_offsets[e0] + g_rs[2*t]) * DIM;
    size_t r1 = (size_t)(g_offsets[e1] + g_rs[2*t+1]) * DIM;
    float al = alpha[0];
    float w0 = g_rg[2*t] * al, w1 = g_rg[2*t+1] * al;
    const float4* h4 = (const float4*)(Xh + (size_t)t * DIM);
    const __nv_bfloat16* d0 = g_D + r0;
    const __nv_bfloat16* d1 = g_D + r1;
    float4* o4 = (float4*)(out + (size_t)t * DIM);
    for (int i = threadIdx.x; i < DIM/4; i += blockDim.x) {
        float4 h = h4[i];
        uint2 a2 = *(const uint2*)(d0 + i*4);
        uint2 b2 = *(const uint2*)(d1 + i*4);
        float2 a0 = __bfloat1622float2(*reinterpret_cast<__nv_bfloat162*>(&a2.x));
        float2 a1 = __bfloat1622float2(*reinterpret_cast<__nv_bfloat162*>(&a2.y));
        float2 b0 = __bfloat1622float2(*reinterpret_cast<__nv_bfloat162*>(&b2.x));
        float2 b1 = __bfloat1622float2(*reinterpret_cast<__nv_bfloat162*>(&b2.y));
        float4 r;
        r.x = h.x + w0*a0.x + w1*b0.x;
        r.y = h.y + w0*a0.y + w1*b0.y;
        r.z = h.z + w0*a1.x + w1*b1.x;
        r.w = h.w + w0*a1.y + w1*b1.y;
        o4[i] = r;
    }
}

// ------------------------------- launcher -----------------------------------
extern "C" void kernel_launch(void* const* d_in, const int* in_sizes, int n_in,
                              void* d_out, int out_size) {
    const float* X      = (const float*)d_in[0];
    const float* Wg     = (const float*)d_in[1];
    const float* gate_w = (const float*)d_in[2];
    const float* gate_A = (const float*)d_in[3];
    const float* gate_B = (const float*)d_in[4];
    const float* up_w   = (const float*)d_in[5];
    const float* up_A   = (const float*)d_in[6];
    const float* up_B   = (const float*)d_in[7];
    const float* down_w = (const float*)d_in[8];
    const float* down_A = (const float*)d_in[9];
    const float* down_B = (const float*)d_in[10];
    const float* alpha  = (const float*)d_in[11];
    float* out = (float*)d_out;

    cudaFuncSetAttribute(fused_gemm_kernel,
                         cudaFuncAttributeMaxDynamicSharedMemorySize, FUSED_SMEM);

    __nv_bfloat16 *dWgb, *dWub, *dWdb;
    cudaGetSymbolAddress((void**)&dWgb, g_Wgb);
    cudaGetSymbolAddress((void**)&dWub, g_Wub);
    cudaGetSymbolAddress((void**)&dWdb, g_Wdb);

    // 0: fold + router + dense X conversion
    dim3 frgrid(DIM/128, DIM/64, 3*NE + 3);
    fold_router_kernel<<<frgrid, 256>>>(X, Wg,
                                        gate_w, gate_A, gate_B,
                                        up_w,   up_A,   up_B,
                                        down_w, down_A, down_B,
                                        dWgb, dWub, dWdb);

    // 1: fused gu + down GEMM (gu blocks first, d blocks gated per tile)
    fused_gemm_kernel<<<NGU + ND, 256, FUSED_SMEM>>>();

    // 2: combine (+loss, +state reset)
    combine_kernel<<<T_TOK, 256>>>(X, alpha, out, out_size - 1);
}

// round 16
// speedup vs baseline: 1.0485x; 1.0034x over previous
#include <cuda_runtime.h>
#include <cuda_bf16.h>
#include <math.h>
#include <stdint.h>

// ---------------------------------------------------------------------------
// MoE + LoRA forward, routed top-2/8. Legacy mma.sync bf16 tensor path.
// Round 16: fold thread-map rework (16 rows x 512 k tiles; warp-contiguous
// 256B/row LDG + 128B/row STG => L1 wavefronts halved). Router/xconv/GEMMs/
// combine identical to the 1350us baseline.
// 3 launches: fold(+router+xconv), fused_gemm (gu->d gated), combine.
// ---------------------------------------------------------------------------

#define DIM    2048
#define T_TOK  8192
#define NE     8
#define NR     16
#define NROWS  (T_TOK*2)
#define PADROWS (NROWS + NE*128)      // per-expert counts padded to 128
#define MAXTILES (PADROWS/128)        // 136
#define SCALING 2.0f
#define AUXC   0.01f
#define ZC     0.001f

#define BK 64
#define NS 32                              // 2048 / 64 K-stages
#define GU_STG (128*64 + 64*64 + 64*64)    // halves/stage: A + Bg + Bu
#define D_STG  (128*64 + 128*64)           // halves/stage: A + B
#define FUSED_SMEM (3*GU_STG*2 + 512)      // max(gu, d) + toks
#define NGU (32*MAXTILES)                  // 4352 gu blocks
#define ND  (16*MAXTILES)                  // 2176 d blocks

// ------------------------- scratch (device globals) ------------------------
// Zero-initialized at module load; combine re-zeroes routing state + tile
// counters each call, so every graph replay starts clean.
__device__ int   g_counts[NE];
__device__ int   g_offsets[NE+1];     // published by fused kernel for combine
__device__ float g_importance[NE];
__device__ float g_zsum;
__device__ int   g_tilecnt[MAXTILES]; // gu-CTAs-finished count per row tile
__device__ int   g_tok[NE*T_TOK];
__device__ int   g_re[NROWS];
__device__ int   g_rs[NROWS];
__device__ float g_rg[NROWS];

__device__ __nv_bfloat16 g_Xb[(size_t)T_TOK*DIM];      // dense bf16 X
__device__ __nv_bfloat16 g_Wgb[(size_t)NE*DIM*DIM];    // folded bf16 weights
__device__ __nv_bfloat16 g_Wub[(size_t)NE*DIM*DIM];
__device__ __nv_bfloat16 g_Wdb[(size_t)NE*DIM*DIM];

__device__ __nv_bfloat16 g_A2[(size_t)PADROWS*DIM];    // silu(g)*u
__device__ __nv_bfloat16 g_D[(size_t)PADROWS*DIM];     // down output (bf16)

// ------------------------------- helpers -----------------------------------
__device__ __forceinline__ uint2 cvt4(float4 v) {
    __nv_bfloat162 lo = __floats2bfloat162_rn(v.x, v.y);
    __nv_bfloat162 hi = __floats2bfloat162_rn(v.z, v.w);
    uint2 r;
    r.x = *reinterpret_cast<unsigned*>(&lo);
    r.y = *reinterpret_cast<unsigned*>(&hi);
    return r;
}

__device__ __forceinline__ void mma16816(float* d, const unsigned* a, const unsigned* b) {
    asm volatile(
        "mma.sync.aligned.m16n8k16.row.col.f32.bf16.bf16.f32 "
        "{%0,%1,%2,%3}, {%4,%5,%6,%7}, {%8,%9}, {%0,%1,%2,%3};\n"
        : "+f"(d[0]), "+f"(d[1]), "+f"(d[2]), "+f"(d[3])
        : "r"(a[0]), "r"(a[1]), "r"(a[2]), "r"(a[3]), "r"(b[0]), "r"(b[1]));
}

__device__ __forceinline__ void ldsm4(unsigned &r0, unsigned &r1, unsigned &r2,
                                      unsigned &r3, uint32_t addr) {
    asm volatile("ldmatrix.sync.aligned.m8n8.x4.shared.b16 {%0,%1,%2,%3}, [%4];\n"
                 : "=r"(r0), "=r"(r1), "=r"(r2), "=r"(r3) : "r"(addr));
}

__device__ __forceinline__ void cpa16(uint32_t dst, const void* src) {
    asm volatile("cp.async.cg.shared.global [%0], [%1], 16;\n" :: "r"(dst), "l"(src));
}
__device__ __forceinline__ void cpa16z(uint32_t dst, const void* src, int sz) {
    asm volatile("cp.async.cg.shared.global [%0], [%1], 16, %2;\n"
                 :: "r"(dst), "l"(src), "r"(sz));
}
#define CP_COMMIT asm volatile("cp.async.commit_group;\n")
template<int N> __device__ __forceinline__ void cp_wait() {
    asm volatile("cp.async.wait_group %0;\n" :: "n"(N));
}

// packed fp32x2 helpers
__device__ __forceinline__ void fma2(uint64_t& d, uint64_t a, uint64_t b) {
    asm("fma.rn.f32x2 %0, %1, %2, %3;" : "=l"(d) : "l"(a), "l"(b), "l"(d));
}
__device__ __forceinline__ uint64_t packf2(float lo, float hi) {
    uint64_t r;
    asm("mov.b64 %0, {%1, %2};" : "=l"(r) : "f"(lo), "f"(hi));
    return r;
}
__device__ __forceinline__ void unpackf2(uint64_t p, float& lo, float& hi) {
    asm("mov.b64 {%0, %1}, %2;" : "=f"(lo), "=f"(hi) : "l"(p));
}

// local padded-offset derivation from g_counts
__device__ __forceinline__ int make_offs(int* offs) {
    int o = 0;
#pragma unroll
    for (int e = 0; e < NE; e++) {
        offs[e] = o;
        o += ((g_counts[e] + 127) >> 7) << 7;
    }
    offs[NE] = o;
    return o;
}

// ---- fold + router + xconv fused launch (z: 0-1 router, 2 xconv, 3+ fold) --
// Fold tile: 16 rows x 512 k. Warp footprint per LDG.128: 2 rows x 256B
// contiguous (4 L1 wavefronts); STG.64: 2 rows x 128B (2 wavefronts).
__global__ __launch_bounds__(256) void fold_router_kernel(
        const float* __restrict__ X,   const float* __restrict__ Wgate,
        const float* __restrict__ Wg_, const float* __restrict__ Ag_,
        const float* __restrict__ Bg_,
        const float* __restrict__ Wu_, const float* __restrict__ Au_,
        const float* __restrict__ Bu_,
        const float* __restrict__ Wd_, const float* __restrict__ Ad_,
        const float* __restrict__ Bd_,
        __nv_bfloat16* __restrict__ Og_, __nv_bfloat16* __restrict__ Ou_,
        __nv_bfloat16* __restrict__ Od_) {
    int z = blockIdx.z;
    if (z < 2) {
        // ---------------- router path ----------------
        int rblk = z * 512 + blockIdx.y * 4 + blockIdx.x;    // 0..1023
        int warp = threadIdx.x >> 5, lane = threadIdx.x & 31;
        int t = rblk * 8 + warp;
        if (t >= T_TOK) return;
        const float4* xr = (const float4*)(X + (size_t)t * DIM);
        float acc[NE];
#pragma unroll
        for (int e = 0; e < NE; e++) acc[e] = 0.f;
        for (int i = lane; i < DIM/4; i += 32) {
            float4 xv = xr[i];
#pragma unroll
            for (int e = 0; e < NE; e++) {
                float4 w = ((const float4*)(Wgate + (size_t)e * DIM))[i];
                acc[e] += xv.x*w.x + xv.y*w.y + xv.z*w.z + xv.w*w.w;
            }
        }
#pragma unroll
        for (int e = 0; e < NE; e++)
#pragma unroll
            for (int o = 16; o > 0; o >>= 1)
                acc[e] += __shfl_xor_sync(0xffffffffu, acc[e], o);

        if (lane == 0) {
            int e0 = 0;
#pragma unroll
            for (int e = 1; e < NE; e++) if (acc[e] > acc[e0]) e0 = e;
            int e1 = (e0 == 0) ? 1 : 0;
#pragma unroll
            for (int e = 0; e < NE; e++)
                if (e != e0 && acc[e] > acc[e1]) e1 = e;

            float m = acc[e0];
            float s = 0.f;
#pragma unroll
            for (int e = 0; e < NE; e++) s += expf(acc[e] - m);
            float lse = logf(s) + m;
            atomicAdd(&g_zsum, lse * lse);

            float d = expf(acc[e1] - acc[e0]);
            float p0 = 1.f / (1.f + d);
            float p1 = d / (1.f + d);

            int s0 = atomicAdd(&g_counts[e0], 1);
            int s1 = atomicAdd(&g_counts[e1], 1);
            g_tok[e0*T_TOK + s0] = t;
            g_tok[e1*T_TOK + s1] = t;
            atomicAdd(&g_importance[e0], p0);
            atomicAdd(&g_importance[e1], p1);
            g_re[2*t] = e0;  g_rs[2*t] = s0;  g_rg[2*t] = p0;
            g_re[2*t+1] = e1; g_rs[2*t+1] = s1; g_rg[2*t+1] = p1;
        }
        return;
    }
    if (z == 2) {
        // ---------------- dense X fp32 -> bf16 ----------------
        int b = blockIdx.y * 4 + blockIdx.x;    // 0..511
        const float4* src = (const float4*)X;
        uint2* dst = (uint2*)g_Xb;
        int base = b * 8192 + threadIdx.x;      // float4 units
#pragma unroll
        for (int i = 0; i < 32; i++)
            dst[base + i*256] = cvt4(src[base + i*256]);
        return;
    }

    // ---------------- fold path: W' = bf16(W + SCALING * B @ A) ----------------
    int zz = z - 3;
    int wsel = zz >> 3;          // 0=gate, 1=up, 2=down
    int e = zz & 7;
    const float* W = (wsel == 0) ? Wg_ : (wsel == 1) ? Wu_ : Wd_;
    const float* A = (wsel == 0) ? Ag_ : (wsel == 1) ? Au_ : Ad_;
    const float* B = (wsel == 0) ? Bg_ : (wsel == 1) ? Bu_ : Bd_;
    __nv_bfloat16* out = (wsel == 0) ? Og_ : (wsel == 1) ? Ou_ : Od_;

    int tid = threadIdx.x;
    int n  = blockIdx.y * 16 + (tid >> 4);     // 16 rows per block
    int k0 = blockIdx.x * 512;                 // 512 k per block

    __shared__ float As[NR][512];
#pragma unroll
    for (int i = 0; i < 32; i++) {
        int idx = tid + i * 256;               // 8192 = 16 r x 512 k
        As[idx >> 9][idx & 511] = A[((size_t)e*NR + (idx >> 9))*DIM + k0 + (idx & 511)];
    }
    __syncthreads();

    uint64_t Brp[NR];
    {
        const float4* b4 = (const float4*)(B + ((size_t)e*DIM + n)*NR);
#pragma unroll
        for (int q = 0; q < 4; q++) {
            float4 v = b4[q];
            Brp[q*4+0] = packf2(SCALING * v.x, SCALING * v.x);
            Brp[q*4+1] = packf2(SCALING * v.y, SCALING * v.y);
            Brp[q*4+2] = packf2(SCALING * v.z, SCALING * v.z);
            Brp[q*4+3] = packf2(SCALING * v.w, SCALING * v.w);
        }
    }

    const float* Wrow = W + ((size_t)e*DIM + n)*DIM + k0;
    __nv_bfloat16* Orow = out + ((size_t)e*DIM + n)*DIM + k0;
#pragma unroll
    for (int q = 0; q < 8; q++) {
        int k = q*64 + (tid & 15)*4;           // warp: 2 rows x 256B contiguous
        float4 w = *(const float4*)(Wrow + k);
        uint64_t p01 = packf2(w.x, w.y);
        uint64_t p23 = packf2(w.z, w.w);
#pragma unroll
        for (int r = 0; r < NR; r++) {
            uint64_t a01 = *(const uint64_t*)&As[r][k];
            uint64_t a23 = *(const uint64_t*)&As[r][k+2];
            fma2(p01, Brp[r], a01);
            fma2(p23, Brp[r], a23);
        }
        float f0, f1, f2, f3;
        unpackf2(p01, f0, f1);
        unpackf2(p23, f2, f3);
        __nv_bfloat162 lo = __floats2bfloat162_rn(f0, f1);
        __nv_bfloat162 hi = __floats2bfloat162_rn(f2, f3);
        uint2 o;
        o.x = *reinterpret_cast<unsigned*>(&lo);
        o.y = *reinterpret_cast<unsigned*>(&hi);
        *(uint2*)(Orow + k) = o;
    }
}

// ------------------- fused gu + down GEMM (one launch) -----------------------
// Blocks [0, NGU): gate+up GEMM (signals g_tilecnt[tile] on completion).
// Blocks [NGU, NGU+ND): down GEMM (waits for tilecnt[tile]==32 first).
// gu blocks precede d blocks in the grid => dispatch order guarantees progress.
__global__ __launch_bounds__(256, 2) void fused_gemm_kernel() {
    int offs[NE+1];
    int total = make_offs(offs);
    int tid = threadIdx.x;

    extern __shared__ __nv_bfloat16 smem[];
    uint32_t smBase = (uint32_t)__cvta_generic_to_shared(smem);

    if (blockIdx.x < NGU) {
        // =========================== gu path ===========================
        int tile = blockIdx.x >> 5;            // blocks tile-major: tile*32+n
        if (tile * 128 >= total) return;
        int n0 = (blockIdx.x & 31) * 64;
        int e = 0;
#pragma unroll
        for (int q = 0; q < NE; q++)
            if (tile * 128 >= offs[q]) e = q;
        int cnt = g_counts[e];
        int base_slot = tile * 128 - offs[e];
        int rowbase = tile * 128;

        int* toks = (int*)(smem + 3*GU_STG);
        if (tid < 128) {
            int slot = base_slot + tid;
            toks[tid] = (slot < cnt) ? g_tok[e*T_TOK + slot] : -1;
        }
        __syncthreads();

        auto loadStage = [&](int s) {
            uint32_t buf = smBase + (uint32_t)(s % 3) * (GU_STG * 2);
            int k0 = s * BK;
#pragma unroll
            for (int it = 0; it < 4; it++) {           // A: gathered
                int c = tid + it * 256;
                int row = c >> 3, ch = c & 7;
                uint32_t d = buf + (uint32_t)(row*64 + ((ch ^ (row & 7)) * 8)) * 2;
                int tk = toks[row];
                const __nv_bfloat16* src =
                    g_Xb + (size_t)(tk < 0 ? 0 : tk)*DIM + k0 + ch*8;
                cpa16z(d, src, (tk < 0) ? 0 : 16);
            }
#pragma unroll
            for (int it = 0; it < 2; it++) {           // Bg
                int c = tid + it * 256;
                int row = c >> 3, ch = c & 7;
                uint32_t d = buf + (uint32_t)(8192 + row*64 + ((ch ^ (row & 7)) * 8)) * 2;
                cpa16(d, g_Wgb + ((size_t)e*DIM + n0 + row)*DIM + k0 + ch*8);
            }
#pragma unroll
            for (int it = 0; it < 2; it++) {           // Bu
                int c = tid + it * 256;
                int row = c >> 3, ch = c & 7;
                uint32_t d = buf + (uint32_t)(12288 + row*64 + ((ch ^ (row & 7)) * 8)) * 2;
                cpa16(d, g_Wub + ((size_t)e*DIM + n0 + row)*DIM + k0 + ch*8);
            }
        };

        float ag[2][4][4], au[2][4][4];
#pragma unroll
        for (int mt = 0; mt < 2; mt++)
#pragma unroll
            for (int nt = 0; nt < 4; nt++)
#pragma unroll
                for (int i = 0; i < 4; i++) { ag[mt][nt][i] = 0.f; au[mt][nt][i] = 0.f; }

        int lane = tid & 31, warp = tid >> 5;
        int wm = warp & 3, wn = warp >> 2;

        loadStage(0); CP_COMMIT;
        loadStage(1); CP_COMMIT;

        for (int s = 0; s < NS; s++) {
            cp_wait<1>();
            __syncthreads();
            if (s + 2 < NS) loadStage(s + 2);
            CP_COMMIT;

            uint32_t buf = smBase + (uint32_t)(s % 3) * (GU_STG * 2);
#pragma unroll
            for (int kk = 0; kk < BK; kk += 16) {
                int kh = kk + ((lane >> 4) << 3);
                unsigned af[2][4];
#pragma unroll
                for (int mt = 0; mt < 2; mt++) {
                    int arow = wm*32 + mt*16 + (lane & 15);
                    uint32_t a = buf + (uint32_t)(arow*64 +
                                  (((kh >> 3) ^ (arow & 7)) << 3)) * 2;
                    ldsm4(af[mt][0], af[mt][1], af[mt][2], af[mt][3], a);
                }
                unsigned bg[4][2];
#pragma unroll
                for (int p = 0; p < 2; p++) {
                    int brow = wn*32 + p*16 + (lane & 15);
                    uint32_t b = buf + (uint32_t)(8192 + brow*64 +
                                  (((kh >> 3) ^ (brow & 7)) << 3)) * 2;
                    unsigned q0, q1, q2, q3;
                    ldsm4(q0, q1, q2, q3, b);
                    bg[2*p][0] = q0; bg[2*p][1] = q2;
                    bg[2*p+1][0] = q1; bg[2*p+1][1] = q3;
                }
#pragma unroll
                for (int mt = 0; mt < 2; mt++)
#pragma unroll
                    for (int nt = 0; nt < 4; nt++)
                        mma16816(ag[mt][nt], af[mt], bg[nt]);
                unsigned bu[4][2];
#pragma unroll
                for (int p = 0; p < 2; p++) {
                    int brow = wn*32 + p*16 + (lane & 15);
                    uint32_t b = buf + (uint32_t)(12288 + brow*64 +
                                  (((kh >> 3) ^ (brow & 7)) << 3)) * 2;
                    unsigned q0, q1, q2, q3;
                    ldsm4(q0, q1, q2, q3, b);
                    bu[2*p][0] = q0; bu[2*p][1] = q2;
                    bu[2*p+1][0] = q1; bu[2*p+1][1] = q3;
                }
#pragma unroll
                for (int mt = 0; mt < 2; mt++)
#pragma unroll
                    for (int nt = 0; nt < 4; nt++)
                        mma16816(au[mt][nt], af[mt], bu[nt]);
            }
        }

        // epilogue: a = silu(g) * u -> g_A2 bf16
        int g = lane >> 2, t4 = lane & 3;
#pragma unroll
        for (int mt = 0; mt < 2; mt++) {
#pragma unroll
            for (int hrow = 0; hrow < 2; hrow++) {
                int r = wm*32 + mt*16 + g + hrow*8;
                __nv_bfloat16* dst = g_A2 + (size_t)(rowbase + r)*DIM + n0;
#pragma unroll
                for (int nt = 0; nt < 4; nt++) {
                    int c = wn*32 + nt*8 + 2*t4;
                    float g0 = ag[mt][nt][hrow*2 + 0];
                    float g1 = ag[mt][nt][hrow*2 + 1];
                    float u0 = au[mt][nt][hrow*2 + 0];
                    float u1 = au[mt][nt][hrow*2 + 1];
                    float a0 = g0 / (1.f + __expf(-g0)) * u0;
                    float a1 = g1 / (1.f + __expf(-g1)) * u1;
                    __nv_bfloat162 p = __floats2bfloat162_rn(a0, a1);
                    *(unsigned*)(dst + c) = *reinterpret_cast<unsigned*>(&p);
                }
            }
        }
        // signal: this tile's n-block is done (release)
        __syncthreads();
        __threadfence();
        if (tid == 0) atomicAdd(&g_tilecnt[tile], 1);
        return;
    }

    // ============================ d path ============================
    int b = blockIdx.x - NGU;
    int tile = b >> 4;                         // blocks tile-major: tile*16+n
    if (blockIdx.x == NGU && tid <= NE)
        g_offsets[tid] = offs[tid];            // publish for combine
    if (tile * 128 >= total) return;
    int n0 = (b & 15) * 128;
    int e = 0;
#pragma unroll
    for (int q = 0; q < NE; q++)
        if (tile * 128 >= offs[q]) e = q;
    int rowbase = tile * 128;

    // wait until all 32 gu blocks of this tile have finished (acquire)
    if (tid == 0) {
        volatile int* cnt = &g_tilecnt[tile];
        while (*cnt < 32) __nanosleep(200);
    }
    __syncthreads();
    __threadfence();

    auto loadStage = [&](int s) {
        uint32_t buf = smBase + (uint32_t)(s % 3) * (D_STG * 2);
        int k0 = s * BK;
#pragma unroll
        for (int it = 0; it < 4; it++) {               // A
            int c = tid + it * 256;
            int row = c >> 3, ch = c & 7;
            uint32_t d = buf + (uint32_t)(row*64 + ((ch ^ (row & 7)) * 8)) * 2;
            cpa16(d, g_A2 + (size_t)(rowbase + row)*DIM + k0 + ch*8);
        }
#pragma unroll
        for (int it = 0; it < 4; it++) {               // B
            int c = tid + it * 256;
            int row = c >> 3, ch = c & 7;
            uint32_t d = buf + (uint32_t)(8192 + row*64 + ((ch ^ (row & 7)) * 8)) * 2;
            cpa16(d, g_Wdb + ((size_t)e*DIM + n0 + row)*DIM + k0 + ch*8);
        }
    };

    float acc[2][8][4];
#pragma unroll
    for (int mt = 0; mt < 2; mt++)
#pragma unroll
        for (int nt = 0; nt < 8; nt++)
#pragma unroll
            for (int i = 0; i < 4; i++) acc[mt][nt][i] = 0.f;

    int lane = tid & 31, warp = tid >> 5;
    int wm = warp & 3, wn = warp >> 2;

    loadStage(0); CP_COMMIT;
    loadStage(1); CP_COMMIT;

    for (int s = 0; s < NS; s++) {
        cp_wait<1>();
        __syncthreads();
        if (s + 2 < NS) loadStage(s + 2);
        CP_COMMIT;

        uint32_t buf = smBase + (uint32_t)(s % 3) * (D_STG * 2);
#pragma unroll
        for (int kk = 0; kk < BK; kk += 16) {
            int kh = kk + ((lane >> 4) << 3);
            unsigned af[2][4];
#pragma unroll
            for (int mt = 0; mt < 2; mt++) {
                int arow = wm*32 + mt*16 + (lane & 15);
                uint32_t a = buf + (uint32_t)(arow*64 +
                              (((kh >> 3) ^ (arow & 7)) << 3)) * 2;
                ldsm4(af[mt][0], af[mt][1], af[mt][2], af[mt][3], a);
            }
            unsigned bq[8][2];
#pragma unroll
            for (int p = 0; p < 4; p++) {
                int brow = wn*64 + p*16 + (lane & 15);
                uint32_t b = buf + (uint32_t)(8192 + brow*64 +
                              (((kh >> 3) ^ (brow & 7)) << 3)) * 2;
                unsigned q0, q1, q2, q3;
                ldsm4(q0, q1, q2, q3, b);
                bq[2*p][0]   = q0; bq[2*p][1]   = q2;
                bq[2*p+1][0] = q1; bq[2*p+1][1] = q3;
            }
#pragma unroll
            for (int mt = 0; mt < 2; mt++)
#pragma unroll
                for (int nt = 0; nt < 8; nt++)
                    mma16816(acc[mt][nt], af[mt], bq[nt]);
        }
    }

    int g = lane >> 2, t4 = lane & 3;
#pragma unroll
    for (int mt = 0; mt < 2; mt++) {
#pragma unroll
        for (int hrow = 0; hrow < 2; hrow++) {
            int r = wm*32 + mt*16 + g + hrow*8;
            __nv_bfloat16* dst = g_D + (size_t)(rowbase + r)*DIM + n0;
#pragma unroll
            for (int nt = 0; nt < 8; nt++) {
                int c = wn*64 + nt*8 + 2*t4;
                __nv_bfloat162 p = __floats2bfloat162_rn(
                    acc[mt][nt][hrow*2], acc[mt][nt][hrow*2 + 1]);
                *(unsigned*)(dst + c) = *reinterpret_cast<unsigned*>(&p);
            }
        }
    }
}

// --------- combine (+loss, +re-init of routing state & tile counters) -------
__global__ void combine_kernel(const float* __restrict__ Xh,
                               const float* __restrict__ alpha,
                               float* __restrict__ out, int lossidx) {
    int t = blockIdx.x;
    if (t == 0 && threadIdx.x == 0) {
        float s = 0.f;
        for (int e = 0; e < NE; e++) s += g_importance[e] * (float)g_counts[e];
        float lb = AUXC * ((float)NE * s / ((float)T_TOK * (float)T_TOK));
        float z  = ZC * (g_zsum / (float)T_TOK);
        out[lossidx] = lb + z;
        for (int e = 0; e < NE; e++) { g_counts[e] = 0; g_importance[e] = 0.f; }
        g_zsum = 0.f;
    }
    if (t < MAXTILES && threadIdx.x == 0) g_tilecnt[t] = 0;   // reset for replay
    int e0 = g_re[2*t], e1 = g_re[2*t+1];
    size_t r0 = (size_t)(g_offsets[e0] + g_rs[2*t]) * DIM;
    size_t r1 = (size_t)(g_offsets[e1] + g_rs[2*t+1]) * DIM;
    float al = alpha[0];
    float w0 = g_rg[2*t] * al, w1 = g_rg[2*t+1] * al;
    const float4* h4 = (const float4*)(Xh + (size_t)t * DIM);
    const __nv_bfloat16* d0 = g_D + r0;
    const __nv_bfloat16* d1 = g_D + r1;
    float4* o4 = (float4*)(out + (size_t)t * DIM);
    for (int i = threadIdx.x; i < DIM/4; i += blockDim.x) {
        float4 h = h4[i];
        uint2 a2 = *(const uint2*)(d0 + i*4);
        uint2 b2 = *(const uint2*)(d1 + i*4);
        float2 a0 = __bfloat1622float2(*reinterpret_cast<__nv_bfloat162*>(&a2.x));
        float2 a1 = __bfloat1622float2(*reinterpret_cast<__nv_bfloat162*>(&a2.y));
        float2 b0 = __bfloat1622float2(*reinterpret_cast<__nv_bfloat162*>(&b2.x));
        float2 b1 = __bfloat1622float2(*reinterpret_cast<__nv_bfloat162*>(&b2.y));
        float4 r;
        r.x = h.x + w0*a0.x + w1*b0.x;
        r.y = h.y + w0*a0.y + w1*b0.y;
        r.z = h.z + w0*a1.x + w1*b1.x;
        r.w = h.w + w0*a1.y + w1*b1.y;
        o4[i] = r;
    }
}

// ------------------------------- launcher -----------------------------------
extern "C" void kernel_launch(void* const* d_in, const int* in_sizes, int n_in,
                              void* d_out, int out_size) {
    const float* X      = (const float*)d_in[0];
    const float* Wg     = (const float*)d_in[1];
    const float* gate_w = (const float*)d_in[2];
    const float* gate_A = (const float*)d_in[3];
    const float* gate_B = (const float*)d_in[4];
    const float* up_w   = (const float*)d_in[5];
    const float* up_A   = (const float*)d_in[6];
    const float* up_B   = (const float*)d_in[7];
    const float* down_w = (const float*)d_in[8];
    const float* down_A = (const float*)d_in[9];
    const float* down_B = (const float*)d_in[10];
    const float* alpha  = (const float*)d_in[11];
    float* out = (float*)d_out;

    cudaFuncSetAttribute(fused_gemm_kernel,
                         cudaFuncAttributeMaxDynamicSharedMemorySize, FUSED_SMEM);

    __nv_bfloat16 *dWgb, *dWub, *dWdb;
    cudaGetSymbolAddress((void**)&dWgb, g_Wgb);
    cudaGetSymbolAddress((void**)&dWub, g_Wub);
    cudaGetSymbolAddress((void**)&dWdb, g_Wdb);

    // 0: fold + router + dense X conversion (fold tile: 16 rows x 512 k)
    dim3 frgrid(DIM/512, DIM/16, 3*NE + 3);
    fold_router_kernel<<<frgrid, 256>>>(X, Wg,
                                        gate_w, gate_A, gate_B,
                                        up_w,   up_A,   up_B,
                                        down_w, down_A, down_B,
                                        dWgb, dWub, dWdb);

    // 1: fused gu + down GEMM (gu blocks first, d blocks gated per tile)
    fused_gemm_kernel<<<NGU + ND, 256, FUSED_SMEM>>>();

    // 2: combine (+loss, +state reset)
    combine_kernel<<<T_TOK, 256>>>(X, alpha, out, out_size - 1);
}

// round 17
// speedup vs baseline: 1.1292x; 1.0770x over previous
#include <cuda_runtime.h>
#include <cuda_bf16.h>
#include <math.h>
#include <stdint.h>

// ---------------------------------------------------------------------------
// MoE + LoRA forward, routed top-2/8. Legacy mma.sync bf16 tensor path.
// Round 17: fold inner loop inverted — A held in registers (64 regs/thread),
// B read from smem as broadcast duplicated (b,b) pairs => LDS wavefronts per
// output halved (4->2). Flat 64-block z-slices: router z0-15, xconv z16-23,
// fold z24-47. GEMMs/combine identical to the 1345us baseline.
// ---------------------------------------------------------------------------

#define DIM    2048
#define T_TOK  8192
#define NE     8
#define NR     16
#define NROWS  (T_TOK*2)
#define PADROWS (NROWS + NE*128)      // per-expert counts padded to 128
#define MAXTILES (PADROWS/128)        // 136
#define SCALING 2.0f
#define AUXC   0.01f
#define ZC     0.001f

#define BK 64
#define NS 32                              // 2048 / 64 K-stages
#define GU_STG (128*64 + 64*64 + 64*64)    // halves/stage: A + Bg + Bu
#define D_STG  (128*64 + 128*64)           // halves/stage: A + B
#define FUSED_SMEM (3*GU_STG*2 + 512)      // max(gu, d) + toks
#define NGU (32*MAXTILES)                  // 4352 gu blocks
#define ND  (16*MAXTILES)                  // 2176 d blocks

// ------------------------- scratch (device globals) ------------------------
// Zero-initialized at module load; combine re-zeroes routing state + tile
// counters each call, so every graph replay starts clean.
__device__ int   g_counts[NE];
__device__ int   g_offsets[NE+1];     // published by fused kernel for combine
__device__ float g_importance[NE];
__device__ float g_zsum;
__device__ int   g_tilecnt[MAXTILES]; // gu-CTAs-finished count per row tile
__device__ int   g_tok[NE*T_TOK];
__device__ int   g_re[NROWS];
__device__ int   g_rs[NROWS];
__device__ float g_rg[NROWS];

__device__ __nv_bfloat16 g_Xb[(size_t)T_TOK*DIM];      // dense bf16 X
__device__ __nv_bfloat16 g_Wgb[(size_t)NE*DIM*DIM];    // folded bf16 weights
__device__ __nv_bfloat16 g_Wub[(size_t)NE*DIM*DIM];
__device__ __nv_bfloat16 g_Wdb[(size_t)NE*DIM*DIM];

__device__ __nv_bfloat16 g_A2[(size_t)PADROWS*DIM];    // silu(g)*u
__device__ __nv_bfloat16 g_D[(size_t)PADROWS*DIM];     // down output (bf16)

// ------------------------------- helpers -----------------------------------
__device__ __forceinline__ uint2 cvt4(float4 v) {
    __nv_bfloat162 lo = __floats2bfloat162_rn(v.x, v.y);
    __nv_bfloat162 hi = __floats2bfloat162_rn(v.z, v.w);
    uint2 r;
    r.x = *reinterpret_cast<unsigned*>(&lo);
    r.y = *reinterpret_cast<unsigned*>(&hi);
    return r;
}

__device__ __forceinline__ void mma16816(float* d, const unsigned* a, const unsigned* b) {
    asm volatile(
        "mma.sync.aligned.m16n8k16.row.col.f32.bf16.bf16.f32 "
        "{%0,%1,%2,%3}, {%4,%5,%6,%7}, {%8,%9}, {%0,%1,%2,%3};\n"
        : "+f"(d[0]), "+f"(d[1]), "+f"(d[2]), "+f"(d[3])
        : "r"(a[0]), "r"(a[1]), "r"(a[2]), "r"(a[3]), "r"(b[0]), "r"(b[1]));
}

__device__ __forceinline__ void ldsm4(unsigned &r0, unsigned &r1, unsigned &r2,
                                      unsigned &r3, uint32_t addr) {
    asm volatile("ldmatrix.sync.aligned.m8n8.x4.shared.b16 {%0,%1,%2,%3}, [%4];\n"
                 : "=r"(r0), "=r"(r1), "=r"(r2), "=r"(r3) : "r"(addr));
}

__device__ __forceinline__ void cpa16(uint32_t dst, const void* src) {
    asm volatile("cp.async.cg.shared.global [%0], [%1], 16;\n" :: "r"(dst), "l"(src));
}
__device__ __forceinline__ void cpa16z(uint32_t dst, const void* src, int sz) {
    asm volatile("cp.async.cg.shared.global [%0], [%1], 16, %2;\n"
                 :: "r"(dst), "l"(src), "r"(sz));
}
#define CP_COMMIT asm volatile("cp.async.commit_group;\n")
template<int N> __device__ __forceinline__ void cp_wait() {
    asm volatile("cp.async.wait_group %0;\n" :: "n"(N));
}

// packed fp32x2 helpers
__device__ __forceinline__ void fma2(uint64_t& d, uint64_t a, uint64_t b) {
    asm("fma.rn.f32x2 %0, %1, %2, %3;" : "=l"(d) : "l"(a), "l"(b), "l"(d));
}
__device__ __forceinline__ uint64_t packf2(float lo, float hi) {
    uint64_t r;
    asm("mov.b64 %0, {%1, %2};" : "=l"(r) : "f"(lo), "f"(hi));
    return r;
}
__device__ __forceinline__ void unpackf2(uint64_t p, float& lo, float& hi) {
    asm("mov.b64 {%0, %1}, %2;" : "=f"(lo), "=f"(hi) : "l"(p));
}

// local padded-offset derivation from g_counts
__device__ __forceinline__ int make_offs(int* offs) {
    int o = 0;
#pragma unroll
    for (int e = 0; e < NE; e++) {
        offs[e] = o;
        o += ((g_counts[e] + 127) >> 7) << 7;
    }
    offs[NE] = o;
    return o;
}

// ---- fold + router + xconv fused launch (flat 64-block z-slices) -----------
// z 0-15: router (1024 blocks). z 16-23: xconv (512). z 24-47: fold (1536).
// Fold: block = 64 n-rows x 1024 k-cols. Thread owns 4 k-cols; A in regs
// (loaded once), B staged duplicated (b,b) in smem (broadcast LDS.128 reads).
__global__ __launch_bounds__(256) void fold_router_kernel(
        const float* __restrict__ X,   const float* __restrict__ Wgate,
        const float* __restrict__ Wg_, const float* __restrict__ Ag_,
        const float* __restrict__ Bg_,
        const float* __restrict__ Wu_, const float* __restrict__ Au_,
        const float* __restrict__ Bu_,
        const float* __restrict__ Wd_, const float* __restrict__ Ad_,
        const float* __restrict__ Bd_,
        __nv_bfloat16* __restrict__ Og_, __nv_bfloat16* __restrict__ Ou_,
        __nv_bfloat16* __restrict__ Od_) {
    int z = blockIdx.z;
    int tid = threadIdx.x;
    if (z < 16) {
        // ---------------- router path ----------------
        int rblk = z * 64 + blockIdx.x;                      // 0..1023
        int warp = tid >> 5, lane = tid & 31;
        int t = rblk * 8 + warp;
        const float4* xr = (const float4*)(X + (size_t)t * DIM);
        float acc[NE];
#pragma unroll
        for (int e = 0; e < NE; e++) acc[e] = 0.f;
        for (int i = lane; i < DIM/4; i += 32) {
            float4 xv = xr[i];
#pragma unroll
            for (int e = 0; e < NE; e++) {
                float4 w = ((const float4*)(Wgate + (size_t)e * DIM))[i];
                acc[e] += xv.x*w.x + xv.y*w.y + xv.z*w.z + xv.w*w.w;
            }
        }
#pragma unroll
        for (int e = 0; e < NE; e++)
#pragma unroll
            for (int o = 16; o > 0; o >>= 1)
                acc[e] += __shfl_xor_sync(0xffffffffu, acc[e], o);

        if (lane == 0) {
            int e0 = 0;
#pragma unroll
            for (int e = 1; e < NE; e++) if (acc[e] > acc[e0]) e0 = e;
            int e1 = (e0 == 0) ? 1 : 0;
#pragma unroll
            for (int e = 0; e < NE; e++)
                if (e != e0 && acc[e] > acc[e1]) e1 = e;

            float m = acc[e0];
            float s = 0.f;
#pragma unroll
            for (int e = 0; e < NE; e++) s += expf(acc[e] - m);
            float lse = logf(s) + m;
            atomicAdd(&g_zsum, lse * lse);

            float d = expf(acc[e1] - acc[e0]);
            float p0 = 1.f / (1.f + d);
            float p1 = d / (1.f + d);

            int s0 = atomicAdd(&g_counts[e0], 1);
            int s1 = atomicAdd(&g_counts[e1], 1);
            g_tok[e0*T_TOK + s0] = t;
            g_tok[e1*T_TOK + s1] = t;
            atomicAdd(&g_importance[e0], p0);
            atomicAdd(&g_importance[e1], p1);
            g_re[2*t] = e0;  g_rs[2*t] = s0;  g_rg[2*t] = p0;
            g_re[2*t+1] = e1; g_rs[2*t+1] = s1; g_rg[2*t+1] = p1;
        }
        return;
    }
    if (z < 24) {
        // ---------------- dense X fp32 -> bf16 ----------------
        int b = (z - 16) * 64 + blockIdx.x;     // 0..511
        const float4* src = (const float4*)X;
        uint2* dst = (uint2*)g_Xb;
        int base = b * 8192 + tid;              // float4 units
#pragma unroll
        for (int i = 0; i < 32; i++)
            dst[base + i*256] = cvt4(src[base + i*256]);
        return;
    }

    // -------- fold path: W' = bf16(W + SCALING * B @ A), A in registers -----
    int zz = z - 24;
    int wsel = zz >> 3;          // 0=gate, 1=up, 2=down
    int e = zz & 7;
    const float* W = (wsel == 0) ? Wg_ : (wsel == 1) ? Wu_ : Wd_;
    const float* A = (wsel == 0) ? Ag_ : (wsel == 1) ? Au_ : Ad_;
    const float* B = (wsel == 0) ? Bg_ : (wsel == 1) ? Bu_ : Bd_;
    __nv_bfloat16* out = (wsel == 0) ? Og_ : (wsel == 1) ? Ou_ : Od_;

    int k0 = (blockIdx.x & 1) * 1024;          // 2 k-chunks
    int n0 = (blockIdx.x >> 1) * 64;           // 32 n-chunks
    int kc = k0 + tid * 4;                     // this thread's 4 k-columns

    // stage B duplicated: Bs[n][2r] = Bs[n][2r+1] = SCALING * B[n0+n][r]
    __shared__ float Bs[64][32];
    {
        int rrow = tid >> 2, rq = (tid & 3) * 4;      // 64 rows x 4 quads
        float4 v = *(const float4*)(B + ((size_t)e*DIM + n0 + rrow)*NR + rq);
        float* d = &Bs[rrow][rq*2];
        d[0] = SCALING*v.x; d[1] = SCALING*v.x;
        d[2] = SCALING*v.y; d[3] = SCALING*v.y;
        d[4] = SCALING*v.z; d[5] = SCALING*v.z;
        d[6] = SCALING*v.w; d[7] = SCALING*v.w;
    }

    // A rows for this thread's k-columns, packed (a_k,a_{k+1}) / (a_{k+2},a_{k+3})
    uint64_t a01[NR], a23[NR];
#pragma unroll
    for (int r = 0; r < NR; r++) {
        float4 av = *(const float4*)(A + ((size_t)e*NR + r)*DIM + kc);
        a01[r] = packf2(av.x, av.y);
        a23[r] = packf2(av.z, av.w);
    }
    __syncthreads();

    const float* Wbase = W + ((size_t)e*DIM + n0)*DIM + kc;
    __nv_bfloat16* Obase = out + ((size_t)e*DIM + n0)*DIM + kc;
#pragma unroll 4
    for (int n = 0; n < 64; n++) {
        float4 w = *(const float4*)(Wbase + (size_t)n*DIM);
        uint64_t p01 = packf2(w.x, w.y);
        uint64_t p23 = packf2(w.z, w.w);
        const ulonglong2* bp = (const ulonglong2*)&Bs[n][0];
#pragma unroll
        for (int r = 0; r < NR/2; r++) {
            ulonglong2 bb = bp[r];              // (b_{2r},b_{2r}),(b_{2r+1},b_{2r+1})
            fma2(p01, bb.x, a01[2*r]);
            fma2(p23, bb.x, a23[2*r]);
            fma2(p01, bb.y, a01[2*r+1]);
            fma2(p23, bb.y, a23[2*r+1]);
        }
        float f0, f1, f2, f3;
        unpackf2(p01, f0, f1);
        unpackf2(p23, f2, f3);
        __nv_bfloat162 lo = __floats2bfloat162_rn(f0, f1);
        __nv_bfloat162 hi = __floats2bfloat162_rn(f2, f3);
        uint2 o;
        o.x = *reinterpret_cast<unsigned*>(&lo);
        o.y = *reinterpret_cast<unsigned*>(&hi);
        *(uint2*)(Obase + (size_t)n*DIM) = o;
    }
}

// ------------------- fused gu + down GEMM (one launch) -----------------------
// Blocks [0, NGU): gate+up GEMM (signals g_tilecnt[tile] on completion).
// Blocks [NGU, NGU+ND): down GEMM (waits for tilecnt[tile]==32 first).
// gu blocks precede d blocks in the grid => dispatch order guarantees progress.
__global__ __launch_bounds__(256, 2) void fused_gemm_kernel() {
    int offs[NE+1];
    int total = make_offs(offs);
    int tid = threadIdx.x;

    extern __shared__ __nv_bfloat16 smem[];
    uint32_t smBase = (uint32_t)__cvta_generic_to_shared(smem);

    if (blockIdx.x < NGU) {
        // =========================== gu path ===========================
        int tile = blockIdx.x >> 5;            // blocks tile-major: tile*32+n
        if (tile * 128 >= total) return;
        int n0 = (blockIdx.x & 31) * 64;
        int e = 0;
#pragma unroll
        for (int q = 0; q < NE; q++)
            if (tile * 128 >= offs[q]) e = q;
        int cnt = g_counts[e];
        int base_slot = tile * 128 - offs[e];
        int rowbase = tile * 128;

        int* toks = (int*)(smem + 3*GU_STG);
        if (tid < 128) {
            int slot = base_slot + tid;
            toks[tid] = (slot < cnt) ? g_tok[e*T_TOK + slot] : -1;
        }
        __syncthreads();

        auto loadStage = [&](int s) {
            uint32_t buf = smBase + (uint32_t)(s % 3) * (GU_STG * 2);
            int k0 = s * BK;
#pragma unroll
            for (int it = 0; it < 4; it++) {           // A: gathered
                int c = tid + it * 256;
                int row = c >> 3, ch = c & 7;
                uint32_t d = buf + (uint32_t)(row*64 + ((ch ^ (row & 7)) * 8)) * 2;
                int tk = toks[row];
                const __nv_bfloat16* src =
                    g_Xb + (size_t)(tk < 0 ? 0 : tk)*DIM + k0 + ch*8;
                cpa16z(d, src, (tk < 0) ? 0 : 16);
            }
#pragma unroll
            for (int it = 0; it < 2; it++) {           // Bg
                int c = tid + it * 256;
                int row = c >> 3, ch = c & 7;
                uint32_t d = buf + (uint32_t)(8192 + row*64 + ((ch ^ (row & 7)) * 8)) * 2;
                cpa16(d, g_Wgb + ((size_t)e*DIM + n0 + row)*DIM + k0 + ch*8);
            }
#pragma unroll
            for (int it = 0; it < 2; it++) {           // Bu
                int c = tid + it * 256;
                int row = c >> 3, ch = c & 7;
                uint32_t d = buf + (uint32_t)(12288 + row*64 + ((ch ^ (row & 7)) * 8)) * 2;
                cpa16(d, g_Wub + ((size_t)e*DIM + n0 + row)*DIM + k0 + ch*8);
            }
        };

        float ag[2][4][4], au[2][4][4];
#pragma unroll
        for (int mt = 0; mt < 2; mt++)
#pragma unroll
            for (int nt = 0; nt < 4; nt++)
#pragma unroll
                for (int i = 0; i < 4; i++) { ag[mt][nt][i] = 0.f; au[mt][nt][i] = 0.f; }

        int lane = tid & 31, warp = tid >> 5;
        int wm = warp & 3, wn = warp >> 2;

        loadStage(0); CP_COMMIT;
        loadStage(1); CP_COMMIT;

        for (int s = 0; s < NS; s++) {
            cp_wait<1>();
            __syncthreads();
            if (s + 2 < NS) loadStage(s + 2);
            CP_COMMIT;

            uint32_t buf = smBase + (uint32_t)(s % 3) * (GU_STG * 2);
#pragma unroll
            for (int kk = 0; kk < BK; kk += 16) {
                int kh = kk + ((lane >> 4) << 3);
                unsigned af[2][4];
#pragma unroll
                for (int mt = 0; mt < 2; mt++) {
                    int arow = wm*32 + mt*16 + (lane & 15);
                    uint32_t a = buf + (uint32_t)(arow*64 +
                                  (((kh >> 3) ^ (arow & 7)) << 3)) * 2;
                    ldsm4(af[mt][0], af[mt][1], af[mt][2], af[mt][3], a);
                }
                unsigned bg[4][2];
#pragma unroll
                for (int p = 0; p < 2; p++) {
                    int brow = wn*32 + p*16 + (lane & 15);
                    uint32_t b = buf + (uint32_t)(8192 + brow*64 +
                                  (((kh >> 3) ^ (brow & 7)) << 3)) * 2;
                    unsigned q0, q1, q2, q3;
                    ldsm4(q0, q1, q2, q3, b);
                    bg[2*p][0] = q0; bg[2*p][1] = q2;
                    bg[2*p+1][0] = q1; bg[2*p+1][1] = q3;
                }
#pragma unroll
                for (int mt = 0; mt < 2; mt++)
#pragma unroll
                    for (int nt = 0; nt < 4; nt++)
                        mma16816(ag[mt][nt], af[mt], bg[nt]);
                unsigned bu[4][2];
#pragma unroll
                for (int p = 0; p < 2; p++) {
                    int brow = wn*32 + p*16 + (lane & 15);
                    uint32_t b = buf + (uint32_t)(12288 + brow*64 +
                                  (((kh >> 3) ^ (brow & 7)) << 3)) * 2;
                    unsigned q0, q1, q2, q3;
                    ldsm4(q0, q1, q2, q3, b);
                    bu[2*p][0] = q0; bu[2*p][1] = q2;
                    bu[2*p+1][0] = q1; bu[2*p+1][1] = q3;
                }
#pragma unroll
                for (int mt = 0; mt < 2; mt++)
#pragma unroll
                    for (int nt = 0; nt < 4; nt++)
                        mma16816(au[mt][nt], af[mt], bu[nt]);
            }
        }

        // epilogue: a = silu(g) * u -> g_A2 bf16
        int g = lane >> 2, t4 = lane & 3;
#pragma unroll
        for (int mt = 0; mt < 2; mt++) {
#pragma unroll
            for (int hrow = 0; hrow < 2; hrow++) {
                int r = wm*32 + mt*16 + g + hrow*8;
                __nv_bfloat16* dst = g_A2 + (size_t)(rowbase + r)*DIM + n0;
#pragma unroll
                for (int nt = 0; nt < 4; nt++) {
                    int c = wn*32 + nt*8 + 2*t4;
                    float g0 = ag[mt][nt][hrow*2 + 0];
                    float g1 = ag[mt][nt][hrow*2 + 1];
                    float u0 = au[mt][nt][hrow*2 + 0];
                    float u1 = au[mt][nt][hrow*2 + 1];
                    float a0 = g0 / (1.f + __expf(-g0)) * u0;
                    float a1 = g1 / (1.f + __expf(-g1)) * u1;
                    __nv_bfloat162 p = __floats2bfloat162_rn(a0, a1);
                    *(unsigned*)(dst + c) = *reinterpret_cast<unsigned*>(&p);
                }
            }
        }
        // signal: this tile's n-block is done (release)
        __syncthreads();
        __threadfence();
        if (tid == 0) atomicAdd(&g_tilecnt[tile], 1);
        return;
    }

    // ============================ d path ============================
    int b = blockIdx.x - NGU;
    int tile = b >> 4;                         // blocks tile-major: tile*16+n
    if (blockIdx.x == NGU && tid <= NE)
        g_offsets[tid] = offs[tid];            // publish for combine
    if (tile * 128 >= total) return;
    int n0 = (b & 15) * 128;
    int e = 0;
#pragma unroll
    for (int q = 0; q < NE; q++)
        if (tile * 128 >= offs[q]) e = q;
    int rowbase = tile * 128;

    // wait until all 32 gu blocks of this tile have finished (acquire)
    if (tid == 0) {
        volatile int* cnt = &g_tilecnt[tile];
        while (*cnt < 32) __nanosleep(200);
    }
    __syncthreads();
    __threadfence();

    auto loadStage = [&](int s) {
        uint32_t buf = smBase + (uint32_t)(s % 3) * (D_STG * 2);
        int k0 = s * BK;
#pragma unroll
        for (int it = 0; it < 4; it++) {               // A
            int c = tid + it * 256;
            int row = c >> 3, ch = c & 7;
            uint32_t d = buf + (uint32_t)(row*64 + ((ch ^ (row & 7)) * 8)) * 2;
            cpa16(d, g_A2 + (size_t)(rowbase + row)*DIM + k0 + ch*8);
        }
#pragma unroll
        for (int it = 0; it < 4; it++) {               // B
            int c = tid + it * 256;
            int row = c >> 3, ch = c & 7;
            uint32_t d = buf + (uint32_t)(8192 + row*64 + ((ch ^ (row & 7)) * 8)) * 2;
            cpa16(d, g_Wdb + ((size_t)e*DIM + n0 + row)*DIM + k0 + ch*8);
        }
    };

    float acc[2][8][4];
#pragma unroll
    for (int mt = 0; mt < 2; mt++)
#pragma unroll
        for (int nt = 0; nt < 8; nt++)
#pragma unroll
            for (int i = 0; i < 4; i++) acc[mt][nt][i] = 0.f;

    int lane = tid & 31, warp = tid >> 5;
    int wm = warp & 3, wn = warp >> 2;

    loadStage(0); CP_COMMIT;
    loadStage(1); CP_COMMIT;

    for (int s = 0; s < NS; s++) {
        cp_wait<1>();
        __syncthreads();
        if (s + 2 < NS) loadStage(s + 2);
        CP_COMMIT;

        uint32_t buf = smBase + (uint32_t)(s % 3) * (D_STG * 2);
#pragma unroll
        for (int kk = 0; kk < BK; kk += 16) {
            int kh = kk + ((lane >> 4) << 3);
            unsigned af[2][4];
#pragma unroll
            for (int mt = 0; mt < 2; mt++) {
                int arow = wm*32 + mt*16 + (lane & 15);
                uint32_t a = buf + (uint32_t)(arow*64 +
                              (((kh >> 3) ^ (arow & 7)) << 3)) * 2;
                ldsm4(af[mt][0], af[mt][1], af[mt][2], af[mt][3], a);
            }
            unsigned bq[8][2];
#pragma unroll
            for (int p = 0; p < 4; p++) {
                int brow = wn*64 + p*16 + (lane & 15);
                uint32_t b = buf + (uint32_t)(8192 + brow*64 +
                              (((kh >> 3) ^ (brow & 7)) << 3)) * 2;
                unsigned q0, q1, q2, q3;
                ldsm4(q0, q1, q2, q3, b);
                bq[2*p][0]   = q0; bq[2*p][1]   = q2;
                bq[2*p+1][0] = q1; bq[2*p+1][1] = q3;
            }
#pragma unroll
            for (int mt = 0; mt < 2; mt++)
#pragma unroll
                for (int nt = 0; nt < 8; nt++)
                    mma16816(acc[mt][nt], af[mt], bq[nt]);
        }
    }

    int g = lane >> 2, t4 = lane & 3;
#pragma unroll
    for (int mt = 0; mt < 2; mt++) {
#pragma unroll
        for (int hrow = 0; hrow < 2; hrow++) {
            int r = wm*32 + mt*16 + g + hrow*8;
            __nv_bfloat16* dst = g_D + (size_t)(rowbase + r)*DIM + n0;
#pragma unroll
            for (int nt = 0; nt < 8; nt++) {
                int c = wn*64 + nt*8 + 2*t4;
                __nv_bfloat162 p = __floats2bfloat162_rn(
                    acc[mt][nt][hrow*2], acc[mt][nt][hrow*2 + 1]);
                *(unsigned*)(dst + c) = *reinterpret_cast<unsigned*>(&p);
            }
        }
    }
}

// --------- combine (+loss, +re-init of routing state & tile counters) -------
__global__ void combine_kernel(const float* __restrict__ Xh,
                               const float* __restrict__ alpha,
                               float* __restrict__ out, int lossidx) {
    int t = blockIdx.x;
    if (t == 0 && threadIdx.x == 0) {
        float s = 0.f;
        for (int e = 0; e < NE; e++) s += g_importance[e] * (float)g_counts[e];
        float lb = AUXC * ((float)NE * s / ((float)T_TOK * (float)T_TOK));
        float z  = ZC * (g_zsum / (float)T_TOK);
        out[lossidx] = lb + z;
        for (int e = 0; e < NE; e++) { g_counts[e] = 0; g_importance[e] = 0.f; }
        g_zsum = 0.f;
    }
    if (t < MAXTILES && threadIdx.x == 0) g_tilecnt[t] = 0;   // reset for replay
    int e0 = g_re[2*t], e1 = g_re[2*t+1];
    size_t r0 = (size_t)(g_offsets[e0] + g_rs[2*t]) * DIM;
    size_t r1 = (size_t)(g_offsets[e1] + g_rs[2*t+1]) * DIM;
    float al = alpha[0];
    float w0 = g_rg[2*t] * al, w1 = g_rg[2*t+1] * al;
    const float4* h4 = (const float4*)(Xh + (size_t)t * DIM);
    const __nv_bfloat16* d0 = g_D + r0;
    const __nv_bfloat16* d1 = g_D + r1;
    float4* o4 = (float4*)(out + (size_t)t * DIM);
    for (int i = threadIdx.x; i < DIM/4; i += blockDim.x) {
        float4 h = h4[i];
        uint2 a2 = *(const uint2*)(d0 + i*4);
        uint2 b2 = *(const uint2*)(d1 + i*4);
        float2 a0 = __bfloat1622float2(*reinterpret_cast<__nv_bfloat162*>(&a2.x));
        float2 a1 = __bfloat1622float2(*reinterpret_cast<__nv_bfloat162*>(&a2.y));
        float2 b0 = __bfloat1622float2(*reinterpret_cast<__nv_bfloat162*>(&b2.x));
        float2 b1 = __bfloat1622float2(*reinterpret_cast<__nv_bfloat162*>(&b2.y));
        float4 r;
        r.x = h.x + w0*a0.x + w1*b0.x;
        r.y = h.y + w0*a0.y + w1*b0.y;
        r.z = h.z + w0*a1.x + w1*b1.x;
        r.w = h.w + w0*a1.y + w1*b1.y;
        o4[i] = r;
    }
}

// ------------------------------- launcher -----------------------------------
extern "C" void kernel_launch(void* const* d_in, const int* in_sizes, int n_in,
                              void* d_out, int out_size) {
    const float* X      = (const float*)d_in[0];
    const float* Wg     = (const float*)d_in[1];
    const float* gate_w = (const float*)d_in[2];
    const float* gate_A = (const float*)d_in[3];
    const float* gate_B = (const float*)d_in[4];
    const float* up_w   = (const float*)d_in[5];
    const float* up_A   = (const float*)d_in[6];
    const float* up_B   = (const float*)d_in[7];
    const float* down_w = (const float*)d_in[8];
    const float* down_A = (const float*)d_in[9];
    const float* down_B = (const float*)d_in[10];
    const float* alpha  = (const float*)d_in[11];
    float* out = (float*)d_out;

    cudaFuncSetAttribute(fused_gemm_kernel,
                         cudaFuncAttributeMaxDynamicSharedMemorySize, FUSED_SMEM);

    __nv_bfloat16 *dWgb, *dWub, *dWdb;
    cudaGetSymbolAddress((void**)&dWgb, g_Wgb);
    cudaGetSymbolAddress((void**)&dWub, g_Wub);
    cudaGetSymbolAddress((void**)&dWdb, g_Wdb);

    // 0: fold + router + dense X conversion (flat 64-block z-slices)
    dim3 frgrid(64, 1, 48);
    fold_router_kernel<<<frgrid, 256>>>(X, Wg,
                                        gate_w, gate_A, gate_B,
                                        up_w,   up_A,   up_B,
                                        down_w, down_A, down_B,
                                        dWgb, dWub, dWdb);

    // 1: fused gu + down GEMM (gu blocks first, d blocks gated per tile)
    fused_gemm_kernel<<<NGU + ND, 256, FUSED_SMEM>>>();

    // 2: combine (+loss, +state reset)
    combine_kernel<<<T_TOK, 256>>>(X, alpha, out, out_size - 1);
}